// round 10
// baseline (speedup 1.0000x reference)
#include <cuda_runtime.h>
#include <cuda_bf16.h>
#include <cstdint>
#include <stdint.h>
#include <math.h>

#define BATCH 2
#define SEQ 2048
#define NH 16
#define HD 128
#define DM 2048
#define MROWS (BATCH*SEQ)     // 4096
#define NQKV (3*DM)           // 6144
#define SCALE 0.08838834764831845f  // 1/sqrt(128)

// ---------------- scratch (static device globals: allocation-free) ----------
// Q/K/V stored pre-split as packed bf16 hi + residual-lo (ushort [b,h,s,d]).
__device__ unsigned short g_Qhi[BATCH*NH*SEQ*HD];
__device__ unsigned short g_Qlo[BATCH*NH*SEQ*HD];
__device__ unsigned short g_Khi[BATCH*NH*SEQ*HD];
__device__ unsigned short g_Klo[BATCH*NH*SEQ*HD];
__device__ unsigned short g_Vhi[BATCH*NH*SEQ*HD];
__device__ unsigned short g_Vlo[BATCH*NH*SEQ*HD];
__device__ float g_ctx[MROWS*DM];        // [b*s, h*d] (tf32-rounded at write)
__device__ float g_cos[SEQ*64];
__device__ float g_sin[SEQ*64];
// tf32-pre-rounded copies of GEMM operands
__device__ float g_Xr[MROWS*DM];         // 33.5 MB
__device__ float g_Wqkvr[NQKV*DM];       // 50.3 MB
__device__ float g_OWr[DM*DM];           // 16.8 MB

// ---------------- RoPE table -------------------------------------------------
__global__ void build_rope_kernel() {
    int idx = blockIdx.x * blockDim.x + threadIdx.x;
    if (idx >= SEQ * 64) return;
    int pos = idx >> 6, i = idx & 63;
    double f = pow(10000.0, -(double)i / 64.0);
    double a = (double)pos * f;
    g_cos[idx] = (float)cos(a);
    g_sin[idx] = (float)sin(a);
}

// ---------------- tf32 / bf16 helpers ---------------------------------------
__device__ __forceinline__ float cvt_tf32(float x) {
    unsigned int r;
    asm("cvt.rna.tf32.f32 %0, %1;" : "=r"(r) : "f"(x));
    return __uint_as_float(r);
}

// elementwise tf32 pre-rounding (float4 grid-stride)
__global__ void round_tf32_kernel(const float* __restrict__ src,
                                  float* __restrict__ dst, int n4) {
    int i = blockIdx.x * blockDim.x + threadIdx.x;
    int stride = gridDim.x * blockDim.x;
    for (; i < n4; i += stride) {
        float4 v = *(const float4*)(src + (size_t)i * 4);
        v.x = cvt_tf32(v.x); v.y = cvt_tf32(v.y);
        v.z = cvt_tf32(v.z); v.w = cvt_tf32(v.w);
        *(float4*)(dst + (size_t)i * 4) = v;
    }
}

__device__ __forceinline__ void mma_tf32_f(float (&cacc)[4],
                                           const float4 &a, const float2 &b) {
    asm volatile(
        "mma.sync.aligned.m16n8k8.row.col.f32.tf32.tf32.f32 "
        "{%0,%1,%2,%3}, {%4,%5,%6,%7}, {%8,%9}, {%0,%1,%2,%3};\n"
        : "+f"(cacc[0]), "+f"(cacc[1]), "+f"(cacc[2]), "+f"(cacc[3])
        : "r"(__float_as_uint(a.x)), "r"(__float_as_uint(a.y)),
          "r"(__float_as_uint(a.z)), "r"(__float_as_uint(a.w)),
          "r"(__float_as_uint(b.x)), "r"(__float_as_uint(b.y)));
}

__device__ __forceinline__ void mma_bf16(float (&cacc)[4],
                                         const unsigned int (&a)[4],
                                         unsigned int b0, unsigned int b1) {
    asm volatile(
        "mma.sync.aligned.m16n8k16.row.col.f32.bf16.bf16.f32 "
        "{%0,%1,%2,%3}, {%4,%5,%6,%7}, {%8,%9}, {%0,%1,%2,%3};\n"
        : "+f"(cacc[0]), "+f"(cacc[1]), "+f"(cacc[2]), "+f"(cacc[3])
        : "r"(a[0]), "r"(a[1]), "r"(a[2]), "r"(a[3]), "r"(b0), "r"(b1));
}

// split two floats into packed bf16 hi pair + bf16 residual-lo pair
__device__ __forceinline__ void split2(float a, float b,
                                       unsigned int &hi, unsigned int &lo) {
    __nv_bfloat16 ha = __float2bfloat16(a);
    __nv_bfloat16 hb = __float2bfloat16(b);
    float ra = a - __bfloat162float(ha);
    float rb = b - __bfloat162float(hb);
    __nv_bfloat16 la = __float2bfloat16(ra);
    __nv_bfloat16 lb = __float2bfloat16(rb);
    hi = (unsigned int)__bfloat16_as_ushort(ha) |
         ((unsigned int)__bfloat16_as_ushort(hb) << 16);
    lo = (unsigned int)__bfloat16_as_ushort(la) |
         ((unsigned int)__bfloat16_as_ushort(lb) << 16);
}

// ---------------- tf32 HMMA 128x256xK NT GEMM mainloop ----------------------
// Inputs pre-rounded to tf32 in gmem -> mainloop stores are raw STS (no CVT).
// 256 threads = 8 warps (2m x 4n), warp tile 64x64 (4 mt x 8 nt m16n8k8).
// Fragment-packed smem: A operand = 1 LDS.128, B operand = 1 LDS.64.
#define GEMM_NTHREADS 256
#define GEMM_SMEM_BYTES (2*16*33*16 + 2*64*33*8)   // Asf + Bsf = 50688

__device__ __forceinline__ void gemm_tf32_mainloop(
    const float* __restrict__ Ag, const float* __restrict__ Bg,
    int K, char* smem, float (&acc)[4][8][4])
{
    float4* Asf = (float4*)smem;                   // [2][16][33]
    float2* Bsf = (float2*)(smem + 2*16*33*16);    // [2][64][33]

    const int tid = threadIdx.x;
    const int lane = tid & 31;
    const int wid = tid >> 5;
    const int mwarp = wid >> 2;        // 0..1
    const int nwarp = wid & 3;         // 0..3
    const int r0 = tid >> 2;           // 0..63
    const int kc0 = (tid & 3) * 4;     // 0,4,8,12
    const int KT = K >> 4;

    // store decomposition (constant across tiles)
    const int ksS = kc0 >> 3;          // k-step
    const int khS = (kc0 >> 2) & 1;    // k-half within step
    const int miS0 = r0 >> 4;
    const int mrS = r0 & 15;
    const int gA = mrS & 7;
    const int compA = (mrS >> 3) + 2 * khS;
    int bBlk[4], gB[4];
    #pragma unroll
    for (int j = 0; j < 4; j++) {
        int nr = r0 + 64 * j;
        int cw = nr >> 7, rem = nr & 127;
        int b64 = (rem >> 6) & 1;
        int qw = (rem >> 5) & 1;
        int t16 = (rem >> 4) & 1;
        int e8 = (rem >> 3) & 1;
        gB[j] = rem & 7;
        int nw = cw * 2 + qw;
        int nt = b64 * 4 + t16 * 2 + e8;
        bBlk[j] = (nw * 8 + nt) * 2 + ksS;
    }

    float4 pa0, pa1, pb[4];
    pa0 = *(const float4*)(Ag + (size_t)r0 * K + kc0);
    pa1 = *(const float4*)(Ag + (size_t)(r0 + 64) * K + kc0);
    #pragma unroll
    for (int j = 0; j < 4; j++)
        pb[j] = *(const float4*)(Bg + (size_t)(r0 + 64 * j) * K + kc0);

    for (int kb = 0; kb < KT; kb++) {
        const int buf = kb & 1;
        // ---- store prefetched regs into fragment-packed smem (raw) ----
        {
            float a0[4] = {pa0.x, pa0.y, pa0.z, pa0.w};
            float a1[4] = {pa1.x, pa1.y, pa1.z, pa1.w};
            float* pA0 = (float*)&Asf[(buf*16 + miS0*2 + ksS)*33 + gA*4] + compA;
            float* pA1 = (float*)&Asf[(buf*16 + (miS0+4)*2 + ksS)*33 + gA*4] + compA;
            #pragma unroll
            for (int j2 = 0; j2 < 4; j2++) {
                pA0[j2 * 4] = a0[j2];
                pA1[j2 * 4] = a1[j2];
            }
            #pragma unroll
            for (int j = 0; j < 4; j++) {
                float b0[4] = {pb[j].x, pb[j].y, pb[j].z, pb[j].w};
                float* pB = (float*)&Bsf[(buf*64 + bBlk[j])*33 + gB[j]*4] + khS;
                #pragma unroll
                for (int j2 = 0; j2 < 4; j2++)
                    pB[j2 * 2] = b0[j2];
            }
        }
        __syncthreads();

        // ---- prefetch next tile ----
        if (kb + 1 < KT) {
            int ko = (kb + 1) * 16 + kc0;
            pa0 = *(const float4*)(Ag + (size_t)r0 * K + ko);
            pa1 = *(const float4*)(Ag + (size_t)(r0 + 64) * K + ko);
            #pragma unroll
            for (int j = 0; j < 4; j++)
                pb[j] = *(const float4*)(Bg + (size_t)(r0 + 64 * j) * K + ko);
        }

        // ---- compute: 2 k-steps x 32 mmas, wide fragment loads ----
        #pragma unroll
        for (int ks = 0; ks < 2; ks++) {
            float4 a4[4];
            float2 b2[8];
            #pragma unroll
            for (int mt = 0; mt < 4; mt++)
                a4[mt] = Asf[(buf*16 + (mwarp*4 + mt)*2 + ks)*33 + lane];
            #pragma unroll
            for (int nt = 0; nt < 8; nt++)
                b2[nt] = Bsf[(buf*64 + (nwarp*8 + nt)*2 + ks)*33 + lane];
            #pragma unroll
            for (int mt = 0; mt < 4; mt++)
                #pragma unroll
                for (int nt = 0; nt < 8; nt++)
                    mma_tf32_f(acc[mt][nt], a4[mt], b2[nt]);
        }
    }
}

// ---------------- QKV GEMM with fused bias + RoPE + bf16-split scatter ------
__global__ void __launch_bounds__(GEMM_NTHREADS) qkv_gemm_kernel(
    const float* __restrict__ bias)
{
    extern __shared__ __align__(16) char smem[];
    float acc[4][8][4];
    #pragma unroll
    for (int i = 0; i < 4; i++)
        #pragma unroll
        for (int j = 0; j < 8; j++)
            #pragma unroll
            for (int k = 0; k < 4; k++) acc[i][j][k] = 0.f;

    const int m0 = blockIdx.y * 128;
    const int n0 = blockIdx.x * 256;
    gemm_tf32_mainloop(g_Xr + (size_t)m0 * DM, g_Wqkvr + (size_t)n0 * DM,
                       DM, smem, acc);

    const int tid = threadIdx.x;
    const int lane = tid & 31;
    const int wid = tid >> 5;
    const int g = lane >> 2, c = lane & 3;
    const int mwarp = wid >> 2, nwarp = wid & 3;
    const int cw = nwarp >> 1, qw = nwarp & 1;

    const int gc = n0 + cw * 128;         // global col of this warp's component
    const int comp = gc >> 11;            // 0=Q, 1=K, 2=V
    const int h = (gc >> 7) & 15;
    unsigned short* dhi = (comp == 0) ? g_Qhi : (comp == 1) ? g_Khi : g_Vhi;
    unsigned short* dlo = (comp == 0) ? g_Qlo : (comp == 1) ? g_Klo : g_Vlo;

    #pragma unroll
    for (int mt = 0; mt < 4; mt++) {
        #pragma unroll
        for (int rr = 0; rr < 2; rr++) {
            int m = m0 + mwarp * 64 + mt * 16 + g + rr * 8;
            int bb = m >> 11, s = m & 2047;
            size_t base = ((size_t)(bb * NH + h) * SEQ + s) * HD;
            #pragma unroll
            for (int nt = 0; nt < 4; nt++) {
                int d0 = qw * 32 + ((nt >> 1) & 1) * 16 + (nt & 1) * 8 + 2 * c;
                float v0e0 = acc[mt][nt][rr * 2]     + bias[gc + d0];
                float v0e1 = acc[mt][nt][rr * 2 + 1] + bias[gc + d0 + 1];
                float v1e0 = acc[mt][nt + 4][rr * 2]     + bias[gc + 64 + d0];
                float v1e1 = acc[mt][nt + 4][rr * 2 + 1] + bias[gc + 64 + d0 + 1];
                unsigned int hi, lo;
                if (comp == 2) {
                    split2(v0e0, v0e1, hi, lo);
                    *(unsigned int*)&dhi[base + d0] = hi;
                    *(unsigned int*)&dlo[base + d0] = lo;
                    split2(v1e0, v1e1, hi, lo);
                    *(unsigned int*)&dhi[base + 64 + d0] = hi;
                    *(unsigned int*)&dlo[base + 64 + d0] = lo;
                } else {
                    float2 cs = *(const float2*)&g_cos[s * 64 + d0];
                    float2 sn = *(const float2*)&g_sin[s * 64 + d0];
                    float q0e0 = v0e0 * cs.x - v1e0 * sn.x;
                    float q0e1 = v0e1 * cs.y - v1e1 * sn.y;
                    float q1e0 = v1e0 * cs.x + v0e0 * sn.x;
                    float q1e1 = v1e1 * cs.y + v0e1 * sn.y;
                    split2(q0e0, q0e1, hi, lo);
                    *(unsigned int*)&dhi[base + d0] = hi;
                    *(unsigned int*)&dlo[base + d0] = lo;
                    split2(q1e0, q1e1, hi, lo);
                    *(unsigned int*)&dhi[base + 64 + d0] = hi;
                    *(unsigned int*)&dlo[base + 64 + d0] = lo;
                }
            }
        }
    }
}

// ---------------- output projection GEMM (reads rounded g_ctx) --------------
__global__ void __launch_bounds__(GEMM_NTHREADS) out_gemm_kernel(
    const float* __restrict__ bias, float* __restrict__ C)
{
    extern __shared__ __align__(16) char smem[];
    float acc[4][8][4];
    #pragma unroll
    for (int i = 0; i < 4; i++)
        #pragma unroll
        for (int j = 0; j < 8; j++)
            #pragma unroll
            for (int k = 0; k < 4; k++) acc[i][j][k] = 0.f;

    const int m0 = blockIdx.y * 128;
    const int n0 = blockIdx.x * 256;
    gemm_tf32_mainloop(g_ctx + (size_t)m0 * DM, g_OWr + (size_t)n0 * DM,
                       DM, smem, acc);

    const int tid = threadIdx.x;
    const int lane = tid & 31;
    const int wid = tid >> 5;
    const int g = lane >> 2, c = lane & 3;
    const int mwarp = wid >> 2, nwarp = wid & 3;
    const int cw = nwarp >> 1, qw = nwarp & 1;

    #pragma unroll
    for (int mt = 0; mt < 4; mt++) {
        #pragma unroll
        for (int rr = 0; rr < 2; rr++) {
            int row = m0 + mwarp * 64 + mt * 16 + g + rr * 8;
            #pragma unroll
            for (int nt = 0; nt < 8; nt++) {
                int colb = n0 + cw * 128 + (nt >> 2) * 64 + qw * 32 +
                           ((nt >> 1) & 1) * 16 + (nt & 1) * 8 + 2 * c;
                float2 st;
                st.x = acc[mt][nt][rr * 2]     + bias[colb];
                st.y = acc[mt][nt][rr * 2 + 1] + bias[colb + 1];
                *(float2*)(C + (size_t)row * DM + colb) = st;
            }
        }
    }
}

// ---------------- tensor-core flash attention (bf16 split-3) ----------------
// Inputs pre-split in gmem (hi/lo ushort). BM=128, BN=64, D=128.
#define QSTR 136   // Q/K smem row stride (bf16 elems)
#define VSTR 72    // Vt/P smem row stride
#define SM_QHI 0
#define SM_QLO (SM_QHI + 128*QSTR)
#define SM_KHI (SM_QLO + 128*QSTR)
#define SM_KLO (SM_KHI + 64*QSTR)
#define SM_VHI (SM_KLO + 64*QSTR)
#define SM_VLO (SM_VHI + 128*VSTR)
#define SM_PHI (SM_VLO + 128*VSTR)
#define SM_PLO (SM_PHI + 128*VSTR)
#define SM_ATTN_ELEMS (SM_PLO + 128*VSTR)

__global__ void __launch_bounds__(256) attn_mma_kernel() {
    extern __shared__ __align__(16) unsigned short sm[];
    unsigned short* Qhi = sm + SM_QHI;
    unsigned short* Qlo = sm + SM_QLO;
    unsigned short* Khi = sm + SM_KHI;
    unsigned short* Klo = sm + SM_KLO;
    unsigned short* Vhi = sm + SM_VHI;   // transposed: [d][s], stride VSTR
    unsigned short* Vlo = sm + SM_VLO;
    unsigned short* Phi = sm + SM_PHI;
    unsigned short* Plo = sm + SM_PLO;

    const int tid = threadIdx.x;
    const int lane = tid & 31;
    const int wid = tid >> 5;
    const int g = lane >> 2;           // 0..7
    const int c = lane & 3;            // 0..3
    const int m0 = wid * 16;
    const int qb = blockIdx.x;         // 0..15
    const int bh = blockIdx.y;         // 0..31
    const int b = bh >> 4, h = bh & 15;

    const size_t bhoff = (size_t)bh * SEQ * HD;
    const unsigned short* Qg_hi = g_Qhi + bhoff + (size_t)qb * 128 * HD;
    const unsigned short* Qg_lo = g_Qlo + bhoff + (size_t)qb * 128 * HD;
    const unsigned short* Kg_hi0 = g_Khi + bhoff;
    const unsigned short* Kg_lo0 = g_Klo + bhoff;
    const unsigned short* Vg_hi0 = g_Vhi + bhoff;
    const unsigned short* Vg_lo0 = g_Vlo + bhoff;

    // ---- load Q (128x128 hi+lo, straight copy) ----
    #pragma unroll
    for (int it = 0; it < 16; it++) {
        int idx = tid + it * 256;                 // 0..4095
        const unsigned short* src = (it < 8) ? Qg_hi : Qg_lo;
        unsigned short* dst = (it < 8) ? Qhi : Qlo;
        int rem = idx & 2047;
        int row = rem >> 4, d = (rem & 15) * 8;
        *(uint4*)&dst[row * QSTR + d] = *(const uint4*)&src[row * HD + d];
    }

    float o[16][4];
    float mrow[2], lrow[2];
    #pragma unroll
    for (int i = 0; i < 16; i++)
        #pragma unroll
        for (int j = 0; j < 4; j++) o[i][j] = 0.f;
    mrow[0] = mrow[1] = -1e30f;
    lrow[0] = lrow[1] = 0.f;

    const int r0 = qb * 128 + m0 + g;
    const int r1 = r0 + 8;

    const int kbmax = 2 * qb + 1;
    for (int kb = 0; kb <= kbmax; kb++) {
        __syncthreads();
        const size_t koff = (size_t)kb * 64 * HD;

        // K tile [64][128] hi+lo: straight copy
        #pragma unroll
        for (int it = 0; it < 8; it++) {
            int idx = tid + it * 256;             // 0..2047
            const unsigned short* src = (it < 4) ? Kg_hi0 : Kg_lo0;
            unsigned short* dst = (it < 4) ? Khi : Klo;
            int rem = idx & 1023;
            int row = rem >> 4, d = (rem & 15) * 8;
            *(uint4*)&dst[row * QSTR + d] = *(const uint4*)&src[koff + row * HD + d];
        }
        // V tile: transpose to [d][s-pairs] via byte_perm
        #pragma unroll
        for (int it = 0; it < 4; it++) {
            int idx = tid + it * 256;             // 0..1023
            const unsigned short* src = (it < 2) ? Vg_hi0 : Vg_lo0;
            unsigned short* dst = (it < 2) ? Vhi : Vlo;
            int rem = idx & 511;
            int s = (rem >> 4) * 2;
            int d = (rem & 15) * 8;
            uint4 ua = *(const uint4*)&src[koff + (size_t)s * HD + d];
            uint4 ub = *(const uint4*)&src[koff + (size_t)(s + 1) * HD + d];
            unsigned int uav[4] = {ua.x, ua.y, ua.z, ua.w};
            unsigned int ubv[4] = {ub.x, ub.y, ub.z, ub.w};
            #pragma unroll
            for (int j = 0; j < 4; j++) {
                unsigned int plo = __byte_perm(uav[j], ubv[j], 0x5410);
                unsigned int phi = __byte_perm(uav[j], ubv[j], 0x7632);
                *(unsigned int*)&dst[(d + 2 * j) * VSTR + s]     = plo;
                *(unsigned int*)&dst[(d + 2 * j + 1) * VSTR + s] = phi;
            }
        }
        __syncthreads();

        // ---- S = Q @ K^T ----
        float sacc[8][4];
        #pragma unroll
        for (int nt = 0; nt < 8; nt++)
            #pragma unroll
            for (int e = 0; e < 4; e++) sacc[nt][e] = 0.f;

        #pragma unroll
        for (int ks = 0; ks < 8; ks++) {
            const int k0 = ks * 16;
            unsigned int ah[4], al[4];
            ah[0] = *(unsigned int*)&Qhi[(m0 + g) * QSTR + k0 + 2 * c];
            ah[1] = *(unsigned int*)&Qhi[(m0 + g + 8) * QSTR + k0 + 2 * c];
            ah[2] = *(unsigned int*)&Qhi[(m0 + g) * QSTR + k0 + 2 * c + 8];
            ah[3] = *(unsigned int*)&Qhi[(m0 + g + 8) * QSTR + k0 + 2 * c + 8];
            al[0] = *(unsigned int*)&Qlo[(m0 + g) * QSTR + k0 + 2 * c];
            al[1] = *(unsigned int*)&Qlo[(m0 + g + 8) * QSTR + k0 + 2 * c];
            al[2] = *(unsigned int*)&Qlo[(m0 + g) * QSTR + k0 + 2 * c + 8];
            al[3] = *(unsigned int*)&Qlo[(m0 + g + 8) * QSTR + k0 + 2 * c + 8];
            #pragma unroll
            for (int nt = 0; nt < 8; nt++) {
                unsigned int bh0 = *(unsigned int*)&Khi[(nt * 8 + g) * QSTR + k0 + 2 * c];
                unsigned int bh1 = *(unsigned int*)&Khi[(nt * 8 + g) * QSTR + k0 + 2 * c + 8];
                unsigned int bl0 = *(unsigned int*)&Klo[(nt * 8 + g) * QSTR + k0 + 2 * c];
                unsigned int bl1 = *(unsigned int*)&Klo[(nt * 8 + g) * QSTR + k0 + 2 * c + 8];
                mma_bf16(sacc[nt], ah, bh0, bh1);
                mma_bf16(sacc[nt], al, bh0, bh1);
                mma_bf16(sacc[nt], ah, bl0, bl1);
            }
        }

        // ---- scale + causal mask + online softmax ----
        float smax0 = -1e30f, smax1 = -1e30f;
        #pragma unroll
        for (int nt = 0; nt < 8; nt++) {
            int col = kb * 64 + nt * 8 + 2 * c;
            float v00 = sacc[nt][0] * SCALE; if (col     > r0) v00 = -1e30f;
            float v01 = sacc[nt][1] * SCALE; if (col + 1 > r0) v01 = -1e30f;
            float v10 = sacc[nt][2] * SCALE; if (col     > r1) v10 = -1e30f;
            float v11 = sacc[nt][3] * SCALE; if (col + 1 > r1) v11 = -1e30f;
            sacc[nt][0] = v00; sacc[nt][1] = v01;
            sacc[nt][2] = v10; sacc[nt][3] = v11;
            smax0 = fmaxf(smax0, fmaxf(v00, v01));
            smax1 = fmaxf(smax1, fmaxf(v10, v11));
        }
        smax0 = fmaxf(smax0, __shfl_xor_sync(0xffffffffu, smax0, 1));
        smax0 = fmaxf(smax0, __shfl_xor_sync(0xffffffffu, smax0, 2));
        smax1 = fmaxf(smax1, __shfl_xor_sync(0xffffffffu, smax1, 1));
        smax1 = fmaxf(smax1, __shfl_xor_sync(0xffffffffu, smax1, 2));

        float mnew0 = fmaxf(mrow[0], smax0);
        float mnew1 = fmaxf(mrow[1], smax1);
        float corr0 = __expf(mrow[0] - mnew0);
        float corr1 = __expf(mrow[1] - mnew1);
        mrow[0] = mnew0; mrow[1] = mnew1;

        float rsum0 = 0.f, rsum1 = 0.f;
        #pragma unroll
        for (int nt = 0; nt < 8; nt++) {
            float p00 = __expf(sacc[nt][0] - mnew0);
            float p01 = __expf(sacc[nt][1] - mnew0);
            float p10 = __expf(sacc[nt][2] - mnew1);
            float p11 = __expf(sacc[nt][3] - mnew1);
            rsum0 += p00 + p01;
            rsum1 += p10 + p11;
            unsigned int hi, lo;
            split2(p00, p01, hi, lo);
            *(unsigned int*)&Phi[(m0 + g) * VSTR + nt * 8 + 2 * c] = hi;
            *(unsigned int*)&Plo[(m0 + g) * VSTR + nt * 8 + 2 * c] = lo;
            split2(p10, p11, hi, lo);
            *(unsigned int*)&Phi[(m0 + g + 8) * VSTR + nt * 8 + 2 * c] = hi;
            *(unsigned int*)&Plo[(m0 + g + 8) * VSTR + nt * 8 + 2 * c] = lo;
        }
        rsum0 += __shfl_xor_sync(0xffffffffu, rsum0, 1);
        rsum0 += __shfl_xor_sync(0xffffffffu, rsum0, 2);
        rsum1 += __shfl_xor_sync(0xffffffffu, rsum1, 1);
        rsum1 += __shfl_xor_sync(0xffffffffu, rsum1, 2);
        lrow[0] = lrow[0] * corr0 + rsum0;
        lrow[1] = lrow[1] * corr1 + rsum1;

        #pragma unroll
        for (int nt = 0; nt < 16; nt++) {
            o[nt][0] *= corr0; o[nt][1] *= corr0;
            o[nt][2] *= corr1; o[nt][3] *= corr1;
        }

        // ---- O += P @ V ----
        #pragma unroll
        for (int ks = 0; ks < 4; ks++) {
            const int k0 = ks * 16;
            unsigned int ah[4], al[4];
            ah[0] = *(unsigned int*)&Phi[(m0 + g) * VSTR + k0 + 2 * c];
            ah[1] = *(unsigned int*)&Phi[(m0 + g + 8) * VSTR + k0 + 2 * c];
            ah[2] = *(unsigned int*)&Phi[(m0 + g) * VSTR + k0 + 2 * c + 8];
            ah[3] = *(unsigned int*)&Phi[(m0 + g + 8) * VSTR + k0 + 2 * c + 8];
            al[0] = *(unsigned int*)&Plo[(m0 + g) * VSTR + k0 + 2 * c];
            al[1] = *(unsigned int*)&Plo[(m0 + g + 8) * VSTR + k0 + 2 * c];
            al[2] = *(unsigned int*)&Plo[(m0 + g) * VSTR + k0 + 2 * c + 8];
            al[3] = *(unsigned int*)&Plo[(m0 + g + 8) * VSTR + k0 + 2 * c + 8];
            #pragma unroll
            for (int nt = 0; nt < 16; nt++) {
                unsigned int bh0 = *(unsigned int*)&Vhi[(nt * 8 + g) * VSTR + k0 + 2 * c];
                unsigned int bh1 = *(unsigned int*)&Vhi[(nt * 8 + g) * VSTR + k0 + 2 * c + 8];
                unsigned int bl0 = *(unsigned int*)&Vlo[(nt * 8 + g) * VSTR + k0 + 2 * c];
                unsigned int bl1 = *(unsigned int*)&Vlo[(nt * 8 + g) * VSTR + k0 + 2 * c + 8];
                mma_bf16(o[nt], ah, bh0, bh1);
                mma_bf16(o[nt], al, bh0, bh1);
                mma_bf16(o[nt], ah, bl0, bl1);
            }
        }
    }

    // ---- normalize + write ctx (pre-rounded to tf32 for out_gemm) ----
    float inv0 = 1.0f / lrow[0];
    float inv1 = 1.0f / lrow[1];
    int s0 = qb * 128 + m0 + g;
    size_t base0 = ((size_t)b * SEQ + s0) * DM + h * HD;
    size_t base1 = ((size_t)b * SEQ + s0 + 8) * DM + h * HD;
    #pragma unroll
    for (int nt = 0; nt < 16; nt++) {
        int d0 = nt * 8 + 2 * c;
        float2 w0, w1;
        w0.x = cvt_tf32(o[nt][0] * inv0);
        w0.y = cvt_tf32(o[nt][1] * inv0);
        w1.x = cvt_tf32(o[nt][2] * inv1);
        w1.y = cvt_tf32(o[nt][3] * inv1);
        *(float2*)(g_ctx + base0 + d0) = w0;
        *(float2*)(g_ctx + base1 + d0) = w1;
    }
}

// ---------------- launch ----------------------------------------------------
extern "C" void kernel_launch(void* const* d_in, const int* in_sizes, int n_in,
                              void* d_out, int out_size) {
    const float* x      = (const float*)d_in[0];
    // d_in[1] = attn_mask (causal, recomputed on the fly; unused)
    const float* Wqkv_w = (const float*)d_in[2];
    const float* Wqkv_b = (const float*)d_in[3];
    const float* out_w  = (const float*)d_in[4];
    const float* out_b  = (const float*)d_in[5];
    float* out = (float*)d_out;

    build_rope_kernel<<<(SEQ * 64 + 255) / 256, 256>>>();

    // pre-round GEMM operands to tf32 (idempotent, bit-identical numerics)
    float* g_Xr_p;    cudaGetSymbolAddress((void**)&g_Xr_p, g_Xr);
    float* g_Wr_p;    cudaGetSymbolAddress((void**)&g_Wr_p, g_Wqkvr);
    float* g_OWr_p;   cudaGetSymbolAddress((void**)&g_OWr_p, g_OWr);
    round_tf32_kernel<<<592, 256>>>(x, g_Xr_p, MROWS * DM / 4);
    round_tf32_kernel<<<592, 256>>>(Wqkv_w, g_Wr_p, NQKV * DM / 4);
    round_tf32_kernel<<<592, 256>>>(out_w, g_OWr_p, DM * DM / 4);

    cudaFuncSetAttribute(qkv_gemm_kernel,
                         cudaFuncAttributeMaxDynamicSharedMemorySize, GEMM_SMEM_BYTES);
    cudaFuncSetAttribute(out_gemm_kernel,
                         cudaFuncAttributeMaxDynamicSharedMemorySize, GEMM_SMEM_BYTES);

    qkv_gemm_kernel<<<dim3(NQKV / 256, MROWS / 128), GEMM_NTHREADS,
                      GEMM_SMEM_BYTES>>>(Wqkv_b);

    const int ATTN_SMEM = SM_ATTN_ELEMS * 2;
    cudaFuncSetAttribute(attn_mma_kernel,
                         cudaFuncAttributeMaxDynamicSharedMemorySize, ATTN_SMEM);
    attn_mma_kernel<<<dim3(SEQ / 128, BATCH * NH), 256, ATTN_SMEM>>>();

    out_gemm_kernel<<<dim3(DM / 256, MROWS / 128), GEMM_NTHREADS,
                      GEMM_SMEM_BYTES>>>(out_b, out);
}

// round 12
// speedup vs baseline: 1.1241x; 1.1241x over previous
#include <cuda_runtime.h>
#include <cuda_bf16.h>
#include <cuda_fp16.h>
#include <cstdint>
#include <stdint.h>
#include <math.h>

#define BATCH 2
#define SEQ 2048
#define NH 16
#define HD 128
#define DM 2048
#define MROWS (BATCH*SEQ)     // 4096
#define NQKV (3*DM)           // 6144
#define SCALE 0.08838834764831845f  // 1/sqrt(128)

// ---------------- scratch (static device globals: allocation-free) ----------
// Q/K/V stored pre-split as packed bf16 hi + residual-lo (ushort [b,h,s,d]).
__device__ unsigned short g_Qhi[BATCH*NH*SEQ*HD];
__device__ unsigned short g_Qlo[BATCH*NH*SEQ*HD];
__device__ unsigned short g_Khi[BATCH*NH*SEQ*HD];
__device__ unsigned short g_Klo[BATCH*NH*SEQ*HD];
__device__ unsigned short g_Vhi[BATCH*NH*SEQ*HD];
__device__ unsigned short g_Vlo[BATCH*NH*SEQ*HD];
__device__ float g_ctx[MROWS*DM];        // [b*s, h*d]
__device__ float g_cos[SEQ*64];
__device__ float g_sin[SEQ*64];

// ---------------- RoPE table -------------------------------------------------
__global__ void build_rope_kernel() {
    int idx = blockIdx.x * blockDim.x + threadIdx.x;
    if (idx >= SEQ * 64) return;
    int pos = idx >> 6, i = idx & 63;
    double f = pow(10000.0, -(double)i / 64.0);
    double a = (double)pos * f;
    g_cos[idx] = (float)cos(a);
    g_sin[idx] = (float)sin(a);
}

// ---------------- fp16 / bf16 helpers ----------------------------------------
__device__ __forceinline__ unsigned f2h2(float lo, float hi) {
    __half2 h = __floats2half2_rn(lo, hi);
    return *(unsigned*)&h;
}

__device__ __forceinline__ void mma_f16(float (&cacc)[4],
                                        const uint4 &a,
                                        unsigned b0, unsigned b1) {
    asm volatile(
        "mma.sync.aligned.m16n8k16.row.col.f32.f16.f16.f32 "
        "{%0,%1,%2,%3}, {%4,%5,%6,%7}, {%8,%9}, {%0,%1,%2,%3};\n"
        : "+f"(cacc[0]), "+f"(cacc[1]), "+f"(cacc[2]), "+f"(cacc[3])
        : "r"(a.x), "r"(a.y), "r"(a.z), "r"(a.w), "r"(b0), "r"(b1));
}

__device__ __forceinline__ void mma_bf16(float (&cacc)[4],
                                         const unsigned int (&a)[4],
                                         unsigned int b0, unsigned int b1) {
    asm volatile(
        "mma.sync.aligned.m16n8k16.row.col.f32.bf16.bf16.f32 "
        "{%0,%1,%2,%3}, {%4,%5,%6,%7}, {%8,%9}, {%0,%1,%2,%3};\n"
        : "+f"(cacc[0]), "+f"(cacc[1]), "+f"(cacc[2]), "+f"(cacc[3])
        : "r"(a[0]), "r"(a[1]), "r"(a[2]), "r"(a[3]), "r"(b0), "r"(b1));
}

// split two floats into packed bf16 hi pair + bf16 residual-lo pair
__device__ __forceinline__ void split2(float a, float b,
                                       unsigned int &hi, unsigned int &lo) {
    __nv_bfloat16 ha = __float2bfloat16(a);
    __nv_bfloat16 hb = __float2bfloat16(b);
    float ra = a - __bfloat162float(ha);
    float rb = b - __bfloat162float(hb);
    __nv_bfloat16 la = __float2bfloat16(ra);
    __nv_bfloat16 lb = __float2bfloat16(rb);
    hi = (unsigned int)__bfloat16_as_ushort(ha) |
         ((unsigned int)__bfloat16_as_ushort(hb) << 16);
    lo = (unsigned int)__bfloat16_as_ushort(la) |
         ((unsigned int)__bfloat16_as_ushort(lb) << 16);
}

// ---------------- fp16 HMMA 128x256xK NT GEMM mainloop ----------------------
// 256 threads = 8 warps (2m x 4n), warp tile 64x64 (4 mt x 8 nt m16n8k16).
// fp16 halves smem traffic vs tf32 (store 12KB + read 32KB per 16-k tile vs
// 24+64) -> smem-BW roofline rises from ~37% to ~74% tensor.
// Fragment-packed smem: A operand = 1 LDS.128 (4x fp16x2 k-pairs),
// B operand = 1 LDS.64. Single __syncthreads per tile, alternating buffers.
#define GEMM_NTHREADS 256
#define ASF_BYTES (2*8*33*16)                 // 8448
#define BSF_BYTES (2*32*33*8)                 // 16896
#define GEMM_SMEM_BYTES (ASF_BYTES + BSF_BYTES)   // 25344

__device__ __forceinline__ void gemm_f16_mainloop(
    const float* __restrict__ Ag, const float* __restrict__ Bg,
    int K, char* smem, float (&acc)[4][8][4])
{
    uint4* Asf = (uint4*)smem;                    // [2][8][33]
    uint2* Bsf = (uint2*)(smem + ASF_BYTES);      // [2][32][33]
    unsigned* Asu = (unsigned*)smem;
    unsigned* Bsu = (unsigned*)(smem + ASF_BYTES);

    const int tid = threadIdx.x;
    const int lane = tid & 31;
    const int wid = tid >> 5;
    const int mwarp = wid >> 2;        // 0..1
    const int nwarp = wid & 3;         // 0..3
    const int r0 = tid >> 2;           // 0..63
    const int kc0 = (tid & 3) * 4;     // 0,4,8,12
    const int KT = K >> 4;

    // store decomposition (constant across tiles)
    const int c0 = (kc0 >> 1) & 3;     // k-pair lane-col {0,2,0,2}
    const int kh = kc0 >> 3;           // k-half {0,0,1,1}
    // A rows r0 (mt 0..3) and r0+64 (mt 4..7)
    const int mtA0 = r0 >> 4;
    const int gA = r0 & 7;
    const int regA = ((r0 >> 3) & 1) + 2 * kh;
    const int idxA0 = (mtA0 * 33 + gA * 4 + c0) * 4 + regA;        // buf 0
    const int idxA1 = ((mtA0 + 4) * 33 + gA * 4 + c0) * 4 + regA;
    // B rows r0 + 64*j
    int idxB[4];
    #pragma unroll
    for (int j = 0; j < 4; j++) {
        int nr = r0 + 64 * j;
        int cw = nr >> 7, rem = nr & 127;
        int b64 = (rem >> 6) & 1;
        int qw = (rem >> 5) & 1;
        int t16 = (rem >> 4) & 1;
        int e8 = (rem >> 3) & 1;
        int gcol = rem & 7;
        int nb = (cw * 2 + qw) * 8 + (b64 * 4 + t16 * 2 + e8);
        idxB[j] = (nb * 33 + gcol * 4 + c0) * 2 + kh;              // buf 0
    }

    float4 pa0, pa1, pb[4];
    pa0 = *(const float4*)(Ag + (size_t)r0 * K + kc0);
    pa1 = *(const float4*)(Ag + (size_t)(r0 + 64) * K + kc0);
    #pragma unroll
    for (int j = 0; j < 4; j++)
        pb[j] = *(const float4*)(Bg + (size_t)(r0 + 64 * j) * K + kc0);

    const int abufu = 8 * 33 * 4;      // u32 per A buffer
    const int bbufu = 32 * 33 * 2;     // u32 per B buffer

    for (int kb = 0; kb < KT; kb++) {
        const int buf = kb & 1;
        // ---- convert + store prefetched regs into fragment-packed smem ----
        {
            int ao = buf * abufu;
            Asu[ao + idxA0]     = f2h2(pa0.x, pa0.y);
            Asu[ao + idxA0 + 4] = f2h2(pa0.z, pa0.w);
            Asu[ao + idxA1]     = f2h2(pa1.x, pa1.y);
            Asu[ao + idxA1 + 4] = f2h2(pa1.z, pa1.w);
            int bo = buf * bbufu;
            #pragma unroll
            for (int j = 0; j < 4; j++) {
                Bsu[bo + idxB[j]]     = f2h2(pb[j].x, pb[j].y);
                Bsu[bo + idxB[j] + 2] = f2h2(pb[j].z, pb[j].w);
            }
        }
        __syncthreads();

        // ---- prefetch next tile ----
        if (kb + 1 < KT) {
            int ko = (kb + 1) * 16 + kc0;
            pa0 = *(const float4*)(Ag + (size_t)r0 * K + ko);
            pa1 = *(const float4*)(Ag + (size_t)(r0 + 64) * K + ko);
            #pragma unroll
            for (int j = 0; j < 4; j++)
                pb[j] = *(const float4*)(Bg + (size_t)(r0 + 64 * j) * K + ko);
        }

        // ---- compute: 32 k16 mmas, wide fragment loads ----
        {
            uint4 a4[4];
            uint2 b2[8];
            #pragma unroll
            for (int mt = 0; mt < 4; mt++)
                a4[mt] = Asf[(buf * 8 + mwarp * 4 + mt) * 33 + lane];
            #pragma unroll
            for (int nt = 0; nt < 8; nt++)
                b2[nt] = Bsf[(buf * 32 + nwarp * 8 + nt) * 33 + lane];
            #pragma unroll
            for (int mt = 0; mt < 4; mt++)
                #pragma unroll
                for (int nt = 0; nt < 8; nt++)
                    mma_f16(acc[mt][nt], a4[mt], b2[nt].x, b2[nt].y);
        }
    }
}

// ---------------- QKV GEMM with fused bias + RoPE + bf16-split scatter ------
__global__ void __launch_bounds__(GEMM_NTHREADS) qkv_gemm_kernel(
    const float* __restrict__ X, const float* __restrict__ W,
    const float* __restrict__ bias)
{
    extern __shared__ __align__(16) char smem[];
    float acc[4][8][4];
    #pragma unroll
    for (int i = 0; i < 4; i++)
        #pragma unroll
        for (int j = 0; j < 8; j++)
            #pragma unroll
            for (int k = 0; k < 4; k++) acc[i][j][k] = 0.f;

    const int m0 = blockIdx.y * 128;
    const int n0 = blockIdx.x * 256;
    gemm_f16_mainloop(X + (size_t)m0 * DM, W + (size_t)n0 * DM, DM, smem, acc);

    const int tid = threadIdx.x;
    const int lane = tid & 31;
    const int wid = tid >> 5;
    const int g = lane >> 2, c = lane & 3;
    const int mwarp = wid >> 2, nwarp = wid & 3;
    const int cw = nwarp >> 1, qw = nwarp & 1;

    const int gc = n0 + cw * 128;         // global col of this warp's component
    const int comp = gc >> 11;            // 0=Q, 1=K, 2=V
    const int h = (gc >> 7) & 15;
    unsigned short* dhi = (comp == 0) ? g_Qhi : (comp == 1) ? g_Khi : g_Vhi;
    unsigned short* dlo = (comp == 0) ? g_Qlo : (comp == 1) ? g_Klo : g_Vlo;

    #pragma unroll
    for (int mt = 0; mt < 4; mt++) {
        #pragma unroll
        for (int rr = 0; rr < 2; rr++) {
            int m = m0 + mwarp * 64 + mt * 16 + g + rr * 8;
            int bb = m >> 11, s = m & 2047;
            size_t base = ((size_t)(bb * NH + h) * SEQ + s) * HD;
            #pragma unroll
            for (int nt = 0; nt < 4; nt++) {
                int d0 = qw * 32 + ((nt >> 1) & 1) * 16 + (nt & 1) * 8 + 2 * c;
                float v0e0 = acc[mt][nt][rr * 2]     + bias[gc + d0];
                float v0e1 = acc[mt][nt][rr * 2 + 1] + bias[gc + d0 + 1];
                float v1e0 = acc[mt][nt + 4][rr * 2]     + bias[gc + 64 + d0];
                float v1e1 = acc[mt][nt + 4][rr * 2 + 1] + bias[gc + 64 + d0 + 1];
                unsigned int hi, lo;
                if (comp == 2) {
                    split2(v0e0, v0e1, hi, lo);
                    *(unsigned int*)&dhi[base + d0] = hi;
                    *(unsigned int*)&dlo[base + d0] = lo;
                    split2(v1e0, v1e1, hi, lo);
                    *(unsigned int*)&dhi[base + 64 + d0] = hi;
                    *(unsigned int*)&dlo[base + 64 + d0] = lo;
                } else {
                    float2 cs = *(const float2*)&g_cos[s * 64 + d0];
                    float2 sn = *(const float2*)&g_sin[s * 64 + d0];
                    float q0e0 = v0e0 * cs.x - v1e0 * sn.x;
                    float q0e1 = v0e1 * cs.y - v1e1 * sn.y;
                    float q1e0 = v1e0 * cs.x + v0e0 * sn.x;
                    float q1e1 = v1e1 * cs.y + v0e1 * sn.y;
                    split2(q0e0, q0e1, hi, lo);
                    *(unsigned int*)&dhi[base + d0] = hi;
                    *(unsigned int*)&dlo[base + d0] = lo;
                    split2(q1e0, q1e1, hi, lo);
                    *(unsigned int*)&dhi[base + 64 + d0] = hi;
                    *(unsigned int*)&dlo[base + 64 + d0] = lo;
                }
            }
        }
    }
}

// ---------------- output projection GEMM (reads g_ctx) ----------------------
__global__ void __launch_bounds__(GEMM_NTHREADS) out_gemm_kernel(
    const float* __restrict__ W, const float* __restrict__ bias,
    float* __restrict__ C)
{
    extern __shared__ __align__(16) char smem[];
    float acc[4][8][4];
    #pragma unroll
    for (int i = 0; i < 4; i++)
        #pragma unroll
        for (int j = 0; j < 8; j++)
            #pragma unroll
            for (int k = 0; k < 4; k++) acc[i][j][k] = 0.f;

    const int m0 = blockIdx.y * 128;
    const int n0 = blockIdx.x * 256;
    gemm_f16_mainloop(g_ctx + (size_t)m0 * DM, W + (size_t)n0 * DM, DM, smem, acc);

    const int tid = threadIdx.x;
    const int lane = tid & 31;
    const int wid = tid >> 5;
    const int g = lane >> 2, c = lane & 3;
    const int mwarp = wid >> 2, nwarp = wid & 3;
    const int cw = nwarp >> 1, qw = nwarp & 1;

    #pragma unroll
    for (int mt = 0; mt < 4; mt++) {
        #pragma unroll
        for (int rr = 0; rr < 2; rr++) {
            int row = m0 + mwarp * 64 + mt * 16 + g + rr * 8;
            #pragma unroll
            for (int nt = 0; nt < 8; nt++) {
                int colb = n0 + cw * 128 + (nt >> 2) * 64 + qw * 32 +
                           ((nt >> 1) & 1) * 16 + (nt & 1) * 8 + 2 * c;
                float2 st;
                st.x = acc[mt][nt][rr * 2]     + bias[colb];
                st.y = acc[mt][nt][rr * 2 + 1] + bias[colb + 1];
                *(float2*)(C + (size_t)row * DM + colb) = st;
            }
        }
    }
}

// ---------------- tensor-core flash attention (bf16 split-3) ----------------
// Inputs pre-split in gmem (hi/lo ushort). BM=128, BN=64, D=128.
#define QSTR 136   // Q/K smem row stride (bf16 elems)
#define VSTR 72    // Vt/P smem row stride
#define SM_QHI 0
#define SM_QLO (SM_QHI + 128*QSTR)
#define SM_KHI (SM_QLO + 128*QSTR)
#define SM_KLO (SM_KHI + 64*QSTR)
#define SM_VHI (SM_KLO + 64*QSTR)
#define SM_VLO (SM_VHI + 128*VSTR)
#define SM_PHI (SM_VLO + 128*VSTR)
#define SM_PLO (SM_PHI + 128*VSTR)
#define SM_ATTN_ELEMS (SM_PLO + 128*VSTR)

__global__ void __launch_bounds__(256) attn_mma_kernel() {
    extern __shared__ __align__(16) unsigned short sm[];
    unsigned short* Qhi = sm + SM_QHI;
    unsigned short* Qlo = sm + SM_QLO;
    unsigned short* Khi = sm + SM_KHI;
    unsigned short* Klo = sm + SM_KLO;
    unsigned short* Vhi = sm + SM_VHI;   // transposed: [d][s], stride VSTR
    unsigned short* Vlo = sm + SM_VLO;
    unsigned short* Phi = sm + SM_PHI;
    unsigned short* Plo = sm + SM_PLO;

    const int tid = threadIdx.x;
    const int lane = tid & 31;
    const int wid = tid >> 5;
    const int g = lane >> 2;           // 0..7
    const int c = lane & 3;            // 0..3
    const int m0 = wid * 16;
    const int qb = blockIdx.x;         // 0..15
    const int bh = blockIdx.y;         // 0..31
    const int b = bh >> 4, h = bh & 15;

    const size_t bhoff = (size_t)bh * SEQ * HD;
    const unsigned short* Qg_hi = g_Qhi + bhoff + (size_t)qb * 128 * HD;
    const unsigned short* Qg_lo = g_Qlo + bhoff + (size_t)qb * 128 * HD;
    const unsigned short* Kg_hi0 = g_Khi + bhoff;
    const unsigned short* Kg_lo0 = g_Klo + bhoff;
    const unsigned short* Vg_hi0 = g_Vhi + bhoff;
    const unsigned short* Vg_lo0 = g_Vlo + bhoff;

    // ---- load Q (128x128 hi+lo, straight copy) ----
    #pragma unroll
    for (int it = 0; it < 16; it++) {
        int idx = tid + it * 256;                 // 0..4095
        const unsigned short* src = (it < 8) ? Qg_hi : Qg_lo;
        unsigned short* dst = (it < 8) ? Qhi : Qlo;
        int rem = idx & 2047;
        int row = rem >> 4, d = (rem & 15) * 8;
        *(uint4*)&dst[row * QSTR + d] = *(const uint4*)&src[row * HD + d];
    }

    float o[16][4];
    float mrow[2], lrow[2];
    #pragma unroll
    for (int i = 0; i < 16; i++)
        #pragma unroll
        for (int j = 0; j < 4; j++) o[i][j] = 0.f;
    mrow[0] = mrow[1] = -1e30f;
    lrow[0] = lrow[1] = 0.f;

    const int r0 = qb * 128 + m0 + g;
    const int r1 = r0 + 8;

    const int kbmax = 2 * qb + 1;
    for (int kb = 0; kb <= kbmax; kb++) {
        __syncthreads();
        const size_t koff = (size_t)kb * 64 * HD;

        // K tile [64][128] hi+lo: straight copy
        #pragma unroll
        for (int it = 0; it < 8; it++) {
            int idx = tid + it * 256;             // 0..2047
            const unsigned short* src = (it < 4) ? Kg_hi0 : Kg_lo0;
            unsigned short* dst = (it < 4) ? Khi : Klo;
            int rem = idx & 1023;
            int row = rem >> 4, d = (rem & 15) * 8;
            *(uint4*)&dst[row * QSTR + d] = *(const uint4*)&src[koff + row * HD + d];
        }
        // V tile: transpose to [d][s-pairs] via byte_perm
        #pragma unroll
        for (int it = 0; it < 4; it++) {
            int idx = tid + it * 256;             // 0..1023
            const unsigned short* src = (it < 2) ? Vg_hi0 : Vg_lo0;
            unsigned short* dst = (it < 2) ? Vhi : Vlo;
            int rem = idx & 511;
            int s = (rem >> 4) * 2;
            int d = (rem & 15) * 8;
            uint4 ua = *(const uint4*)&src[koff + (size_t)s * HD + d];
            uint4 ub = *(const uint4*)&src[koff + (size_t)(s + 1) * HD + d];
            unsigned int uav[4] = {ua.x, ua.y, ua.z, ua.w};
            unsigned int ubv[4] = {ub.x, ub.y, ub.z, ub.w};
            #pragma unroll
            for (int j = 0; j < 4; j++) {
                unsigned int plo = __byte_perm(uav[j], ubv[j], 0x5410);
                unsigned int phi = __byte_perm(uav[j], ubv[j], 0x7632);
                *(unsigned int*)&dst[(d + 2 * j) * VSTR + s]     = plo;
                *(unsigned int*)&dst[(d + 2 * j + 1) * VSTR + s] = phi;
            }
        }
        __syncthreads();

        // ---- S = Q @ K^T ----
        float sacc[8][4];
        #pragma unroll
        for (int nt = 0; nt < 8; nt++)
            #pragma unroll
            for (int e = 0; e < 4; e++) sacc[nt][e] = 0.f;

        #pragma unroll
        for (int ks = 0; ks < 8; ks++) {
            const int k0 = ks * 16;
            unsigned int ah[4], al[4];
            ah[0] = *(unsigned int*)&Qhi[(m0 + g) * QSTR + k0 + 2 * c];
            ah[1] = *(unsigned int*)&Qhi[(m0 + g + 8) * QSTR + k0 + 2 * c];
            ah[2] = *(unsigned int*)&Qhi[(m0 + g) * QSTR + k0 + 2 * c + 8];
            ah[3] = *(unsigned int*)&Qhi[(m0 + g + 8) * QSTR + k0 + 2 * c + 8];
            al[0] = *(unsigned int*)&Qlo[(m0 + g) * QSTR + k0 + 2 * c];
            al[1] = *(unsigned int*)&Qlo[(m0 + g + 8) * QSTR + k0 + 2 * c];
            al[2] = *(unsigned int*)&Qlo[(m0 + g) * QSTR + k0 + 2 * c + 8];
            al[3] = *(unsigned int*)&Qlo[(m0 + g + 8) * QSTR + k0 + 2 * c + 8];
            #pragma unroll
            for (int nt = 0; nt < 8; nt++) {
                unsigned int bh0 = *(unsigned int*)&Khi[(nt * 8 + g) * QSTR + k0 + 2 * c];
                unsigned int bh1 = *(unsigned int*)&Khi[(nt * 8 + g) * QSTR + k0 + 2 * c + 8];
                unsigned int bl0 = *(unsigned int*)&Klo[(nt * 8 + g) * QSTR + k0 + 2 * c];
                unsigned int bl1 = *(unsigned int*)&Klo[(nt * 8 + g) * QSTR + k0 + 2 * c + 8];
                mma_bf16(sacc[nt], ah, bh0, bh1);
                mma_bf16(sacc[nt], al, bh0, bh1);
                mma_bf16(sacc[nt], ah, bl0, bl1);
            }
        }

        // ---- scale + causal mask + online softmax ----
        float smax0 = -1e30f, smax1 = -1e30f;
        #pragma unroll
        for (int nt = 0; nt < 8; nt++) {
            int col = kb * 64 + nt * 8 + 2 * c;
            float v00 = sacc[nt][0] * SCALE; if (col     > r0) v00 = -1e30f;
            float v01 = sacc[nt][1] * SCALE; if (col + 1 > r0) v01 = -1e30f;
            float v10 = sacc[nt][2] * SCALE; if (col     > r1) v10 = -1e30f;
            float v11 = sacc[nt][3] * SCALE; if (col + 1 > r1) v11 = -1e30f;
            sacc[nt][0] = v00; sacc[nt][1] = v01;
            sacc[nt][2] = v10; sacc[nt][3] = v11;
            smax0 = fmaxf(smax0, fmaxf(v00, v01));
            smax1 = fmaxf(smax1, fmaxf(v10, v11));
        }
        smax0 = fmaxf(smax0, __shfl_xor_sync(0xffffffffu, smax0, 1));
        smax0 = fmaxf(smax0, __shfl_xor_sync(0xffffffffu, smax0, 2));
        smax1 = fmaxf(smax1, __shfl_xor_sync(0xffffffffu, smax1, 1));
        smax1 = fmaxf(smax1, __shfl_xor_sync(0xffffffffu, smax1, 2));

        float mnew0 = fmaxf(mrow[0], smax0);
        float mnew1 = fmaxf(mrow[1], smax1);
        float corr0 = __expf(mrow[0] - mnew0);
        float corr1 = __expf(mrow[1] - mnew1);
        mrow[0] = mnew0; mrow[1] = mnew1;

        float rsum0 = 0.f, rsum1 = 0.f;
        #pragma unroll
        for (int nt = 0; nt < 8; nt++) {
            float p00 = __expf(sacc[nt][0] - mnew0);
            float p01 = __expf(sacc[nt][1] - mnew0);
            float p10 = __expf(sacc[nt][2] - mnew1);
            float p11 = __expf(sacc[nt][3] - mnew1);
            rsum0 += p00 + p01;
            rsum1 += p10 + p11;
            unsigned int hi, lo;
            split2(p00, p01, hi, lo);
            *(unsigned int*)&Phi[(m0 + g) * VSTR + nt * 8 + 2 * c] = hi;
            *(unsigned int*)&Plo[(m0 + g) * VSTR + nt * 8 + 2 * c] = lo;
            split2(p10, p11, hi, lo);
            *(unsigned int*)&Phi[(m0 + g + 8) * VSTR + nt * 8 + 2 * c] = hi;
            *(unsigned int*)&Plo[(m0 + g + 8) * VSTR + nt * 8 + 2 * c] = lo;
        }
        rsum0 += __shfl_xor_sync(0xffffffffu, rsum0, 1);
        rsum0 += __shfl_xor_sync(0xffffffffu, rsum0, 2);
        rsum1 += __shfl_xor_sync(0xffffffffu, rsum1, 1);
        rsum1 += __shfl_xor_sync(0xffffffffu, rsum1, 2);
        lrow[0] = lrow[0] * corr0 + rsum0;
        lrow[1] = lrow[1] * corr1 + rsum1;

        #pragma unroll
        for (int nt = 0; nt < 16; nt++) {
            o[nt][0] *= corr0; o[nt][1] *= corr0;
            o[nt][2] *= corr1; o[nt][3] *= corr1;
        }

        // ---- O += P @ V ----
        #pragma unroll
        for (int ks = 0; ks < 4; ks++) {
            const int k0 = ks * 16;
            unsigned int ah[4], al[4];
            ah[0] = *(unsigned int*)&Phi[(m0 + g) * VSTR + k0 + 2 * c];
            ah[1] = *(unsigned int*)&Phi[(m0 + g + 8) * VSTR + k0 + 2 * c];
            ah[2] = *(unsigned int*)&Phi[(m0 + g) * VSTR + k0 + 2 * c + 8];
            ah[3] = *(unsigned int*)&Phi[(m0 + g + 8) * VSTR + k0 + 2 * c + 8];
            al[0] = *(unsigned int*)&Plo[(m0 + g) * VSTR + k0 + 2 * c];
            al[1] = *(unsigned int*)&Plo[(m0 + g + 8) * VSTR + k0 + 2 * c];
            al[2] = *(unsigned int*)&Plo[(m0 + g) * VSTR + k0 + 2 * c + 8];
            al[3] = *(unsigned int*)&Plo[(m0 + g + 8) * VSTR + k0 + 2 * c + 8];
            #pragma unroll
            for (int nt = 0; nt < 16; nt++) {
                unsigned int bh0 = *(unsigned int*)&Vhi[(nt * 8 + g) * VSTR + k0 + 2 * c];
                unsigned int bh1 = *(unsigned int*)&Vhi[(nt * 8 + g) * VSTR + k0 + 2 * c + 8];
                unsigned int bl0 = *(unsigned int*)&Vlo[(nt * 8 + g) * VSTR + k0 + 2 * c];
                unsigned int bl1 = *(unsigned int*)&Vlo[(nt * 8 + g) * VSTR + k0 + 2 * c + 8];
                mma_bf16(o[nt], ah, bh0, bh1);
                mma_bf16(o[nt], al, bh0, bh1);
                mma_bf16(o[nt], ah, bl0, bl1);
            }
        }
    }

    // ---- normalize + write ctx ----
    float inv0 = 1.0f / lrow[0];
    float inv1 = 1.0f / lrow[1];
    int s0 = qb * 128 + m0 + g;
    size_t base0 = ((size_t)b * SEQ + s0) * DM + h * HD;
    size_t base1 = ((size_t)b * SEQ + s0 + 8) * DM + h * HD;
    #pragma unroll
    for (int nt = 0; nt < 16; nt++) {
        int d0 = nt * 8 + 2 * c;
        float2 w0 = {o[nt][0] * inv0, o[nt][1] * inv0};
        float2 w1 = {o[nt][2] * inv1, o[nt][3] * inv1};
        *(float2*)(g_ctx + base0 + d0) = w0;
        *(float2*)(g_ctx + base1 + d0) = w1;
    }
}

// ---------------- launch ----------------------------------------------------
extern "C" void kernel_launch(void* const* d_in, const int* in_sizes, int n_in,
                              void* d_out, int out_size) {
    const float* x      = (const float*)d_in[0];
    // d_in[1] = attn_mask (causal, recomputed on the fly; unused)
    const float* Wqkv_w = (const float*)d_in[2];
    const float* Wqkv_b = (const float*)d_in[3];
    const float* out_w  = (const float*)d_in[4];
    const float* out_b  = (const float*)d_in[5];
    float* out = (float*)d_out;

    build_rope_kernel<<<(SEQ * 64 + 255) / 256, 256>>>();

    cudaFuncSetAttribute(qkv_gemm_kernel,
                         cudaFuncAttributeMaxDynamicSharedMemorySize, GEMM_SMEM_BYTES);
    cudaFuncSetAttribute(out_gemm_kernel,
                         cudaFuncAttributeMaxDynamicSharedMemorySize, GEMM_SMEM_BYTES);

    qkv_gemm_kernel<<<dim3(NQKV / 256, MROWS / 128), GEMM_NTHREADS,
                      GEMM_SMEM_BYTES>>>(x, Wqkv_w, Wqkv_b);

    const int ATTN_SMEM = SM_ATTN_ELEMS * 2;
    cudaFuncSetAttribute(attn_mma_kernel,
                         cudaFuncAttributeMaxDynamicSharedMemorySize, ATTN_SMEM);
    attn_mma_kernel<<<dim3(SEQ / 128, BATCH * NH), 256, ATTN_SMEM>>>();

    out_gemm_kernel<<<dim3(DM / 256, MROWS / 128), GEMM_NTHREADS,
                      GEMM_SMEM_BYTES>>>(out_w, out_b, out);
}

// round 13
// speedup vs baseline: 1.2483x; 1.1104x over previous
#include <cuda_runtime.h>
#include <cuda_bf16.h>
#include <cuda_fp16.h>
#include <cstdint>
#include <stdint.h>
#include <math.h>

#define BATCH 2
#define SEQ 2048
#define NH 16
#define HD 128
#define DM 2048
#define MROWS (BATCH*SEQ)     // 4096
#define NQKV (3*DM)           // 6144
#define SCALE 0.08838834764831845f  // 1/sqrt(128)

// ---------------- scratch (static device globals: allocation-free) ----------
// Q/K/V stored pre-split as packed bf16 hi + residual-lo (ushort [b,h,s,d]).
__device__ unsigned short g_Qhi[BATCH*NH*SEQ*HD];
__device__ unsigned short g_Qlo[BATCH*NH*SEQ*HD];
__device__ unsigned short g_Khi[BATCH*NH*SEQ*HD];
__device__ unsigned short g_Klo[BATCH*NH*SEQ*HD];
__device__ unsigned short g_Vhi[BATCH*NH*SEQ*HD];
__device__ unsigned short g_Vlo[BATCH*NH*SEQ*HD];
__device__ float g_ctx[MROWS*DM];        // [b*s, h*d]
__device__ float g_cos[SEQ*64];
__device__ float g_sin[SEQ*64];

// ---------------- RoPE table -------------------------------------------------
__global__ void build_rope_kernel() {
    int idx = blockIdx.x * blockDim.x + threadIdx.x;
    if (idx >= SEQ * 64) return;
    int pos = idx >> 6, i = idx & 63;
    double f = pow(10000.0, -(double)i / 64.0);
    double a = (double)pos * f;
    g_cos[idx] = (float)cos(a);
    g_sin[idx] = (float)sin(a);
}

// ---------------- fp16 / bf16 helpers ----------------------------------------
__device__ __forceinline__ unsigned f2h2(float lo, float hi) {
    __half2 h = __floats2half2_rn(lo, hi);
    return *(unsigned*)&h;
}

__device__ __forceinline__ void mma_f16(float (&cacc)[4],
                                        const uint4 &a,
                                        unsigned b0, unsigned b1) {
    asm volatile(
        "mma.sync.aligned.m16n8k16.row.col.f32.f16.f16.f32 "
        "{%0,%1,%2,%3}, {%4,%5,%6,%7}, {%8,%9}, {%0,%1,%2,%3};\n"
        : "+f"(cacc[0]), "+f"(cacc[1]), "+f"(cacc[2]), "+f"(cacc[3])
        : "r"(a.x), "r"(a.y), "r"(a.z), "r"(a.w), "r"(b0), "r"(b1));
}

__device__ __forceinline__ void mma_bf16(float (&cacc)[4],
                                         const unsigned int (&a)[4],
                                         unsigned int b0, unsigned int b1) {
    asm volatile(
        "mma.sync.aligned.m16n8k16.row.col.f32.bf16.bf16.f32 "
        "{%0,%1,%2,%3}, {%4,%5,%6,%7}, {%8,%9}, {%0,%1,%2,%3};\n"
        : "+f"(cacc[0]), "+f"(cacc[1]), "+f"(cacc[2]), "+f"(cacc[3])
        : "r"(a[0]), "r"(a[1]), "r"(a[2]), "r"(a[3]), "r"(b0), "r"(b1));
}

// split two floats into packed bf16 hi pair + bf16 residual-lo pair
__device__ __forceinline__ void split2(float a, float b,
                                       unsigned int &hi, unsigned int &lo) {
    __nv_bfloat16 ha = __float2bfloat16(a);
    __nv_bfloat16 hb = __float2bfloat16(b);
    float ra = a - __bfloat162float(ha);
    float rb = b - __bfloat162float(hb);
    __nv_bfloat16 la = __float2bfloat16(ra);
    __nv_bfloat16 lb = __float2bfloat16(rb);
    hi = (unsigned int)__bfloat16_as_ushort(ha) |
         ((unsigned int)__bfloat16_as_ushort(hb) << 16);
    lo = (unsigned int)__bfloat16_as_ushort(la) |
         ((unsigned int)__bfloat16_as_ushort(lb) << 16);
}

// ---------------- fp16 HMMA 128x128xK NT GEMM mainloop ----------------------
// 256 threads = 8 warps (2m x 4n), warp tile 64x32 (4 mt x 4 nt m16n8k16).
// acc = 64 regs -> __launch_bounds__(256,2) gives 2 CTAs/SM: co-resident CTAs
// interleave store/sync/mma phases to fill pipe bubbles (round-12 was 1 CTA).
// Fragment-packed smem: A operand = 1 LDS.128, B operand = 1 LDS.64.
// Warp n-subtile cols: nwarp*16 + (nt&1)*8 + (nt>>1)*64 -> acc[nt], acc[nt+2]
// are the RoPE pair (d, d+64).
#define GEMM_NTHREADS 256
#define ASF_BYTES (2*8*33*16)                 // 8448
#define BSF_BYTES (2*16*33*8)                 // 4224
#define GEMM_SMEM_BYTES (ASF_BYTES + BSF_BYTES)   // 12672

__device__ __forceinline__ void gemm_f16_mainloop(
    const float* __restrict__ Ag, const float* __restrict__ Bg,
    int K, char* smem, float (&acc)[4][4][4])
{
    uint4* Asf = (uint4*)smem;                    // [2][8][33]
    uint2* Bsf = (uint2*)(smem + ASF_BYTES);      // [2][16][33]
    unsigned* Asu = (unsigned*)smem;
    unsigned* Bsu = (unsigned*)(smem + ASF_BYTES);

    const int tid = threadIdx.x;
    const int lane = tid & 31;
    const int wid = tid >> 5;
    const int mwarp = wid >> 2;        // 0..1
    const int nwarp = wid & 3;         // 0..3
    const int r0 = tid >> 2;           // 0..63
    const int kc0 = (tid & 3) * 4;     // 0,4,8,12
    const int KT = K >> 4;

    // store decomposition (constant across tiles)
    const int c0 = (kc0 >> 1) & 3;     // k-pair lane-col {0,2,0,2}
    const int kh = kc0 >> 3;           // k-half {0,0,1,1}
    // A rows r0 (blocks 0..3) and r0+64 (blocks 4..7)
    const int mtA0 = r0 >> 4;
    const int gA = r0 & 7;
    const int regA = ((r0 >> 3) & 1) + 2 * kh;
    const int idxA0 = (mtA0 * 33 + gA * 4 + c0) * 4 + regA;
    const int idxA1 = ((mtA0 + 4) * 33 + gA * 4 + c0) * 4 + regA;
    // B rows r0 + 64*j  (col = nwarp*16 + (nt&1)*8 + (nt>>1)*64 + g)
    int idxB[2];
    #pragma unroll
    for (int j = 0; j < 2; j++) {
        int nr = r0 + 64 * j;          // 0..127
        int rem = nr & 63;
        int nwS = rem >> 4;
        int e8 = (rem >> 3) & 1;
        int gcol = rem & 7;
        int nt = j * 2 + e8;
        int nb = nwS * 4 + nt;
        idxB[j] = (nb * 33 + gcol * 4 + c0) * 2 + kh;
    }

    float4 pa0, pa1, pb0, pb1;
    pa0 = *(const float4*)(Ag + (size_t)r0 * K + kc0);
    pa1 = *(const float4*)(Ag + (size_t)(r0 + 64) * K + kc0);
    pb0 = *(const float4*)(Bg + (size_t)r0 * K + kc0);
    pb1 = *(const float4*)(Bg + (size_t)(r0 + 64) * K + kc0);

    const int abufu = 8 * 33 * 4;      // u32 per A buffer
    const int bbufu = 16 * 33 * 2;     // u32 per B buffer

    for (int kb = 0; kb < KT; kb++) {
        const int buf = kb & 1;
        // ---- convert + store prefetched regs into fragment-packed smem ----
        {
            int ao = buf * abufu;
            Asu[ao + idxA0]     = f2h2(pa0.x, pa0.y);
            Asu[ao + idxA0 + 4] = f2h2(pa0.z, pa0.w);
            Asu[ao + idxA1]     = f2h2(pa1.x, pa1.y);
            Asu[ao + idxA1 + 4] = f2h2(pa1.z, pa1.w);
            int bo = buf * bbufu;
            Bsu[bo + idxB[0]]     = f2h2(pb0.x, pb0.y);
            Bsu[bo + idxB[0] + 2] = f2h2(pb0.z, pb0.w);
            Bsu[bo + idxB[1]]     = f2h2(pb1.x, pb1.y);
            Bsu[bo + idxB[1] + 2] = f2h2(pb1.z, pb1.w);
        }
        __syncthreads();

        // ---- prefetch next tile ----
        if (kb + 1 < KT) {
            int ko = (kb + 1) * 16 + kc0;
            pa0 = *(const float4*)(Ag + (size_t)r0 * K + ko);
            pa1 = *(const float4*)(Ag + (size_t)(r0 + 64) * K + ko);
            pb0 = *(const float4*)(Bg + (size_t)r0 * K + ko);
            pb1 = *(const float4*)(Bg + (size_t)(r0 + 64) * K + ko);
        }

        // ---- compute: 16 k16 mmas, wide fragment loads ----
        {
            uint4 a4[4];
            uint2 b2[4];
            #pragma unroll
            for (int mt = 0; mt < 4; mt++)
                a4[mt] = Asf[(buf * 8 + mwarp * 4 + mt) * 33 + lane];
            #pragma unroll
            for (int nt = 0; nt < 4; nt++)
                b2[nt] = Bsf[(buf * 16 + nwarp * 4 + nt) * 33 + lane];
            #pragma unroll
            for (int mt = 0; mt < 4; mt++)
                #pragma unroll
                for (int nt = 0; nt < 4; nt++)
                    mma_f16(acc[mt][nt], a4[mt], b2[nt].x, b2[nt].y);
        }
    }
}

// ---------------- QKV GEMM with fused bias + RoPE + bf16-split scatter ------
__global__ void __launch_bounds__(GEMM_NTHREADS, 2) qkv_gemm_kernel(
    const float* __restrict__ X, const float* __restrict__ W,
    const float* __restrict__ bias)
{
    extern __shared__ __align__(16) char smem[];
    float acc[4][4][4];
    #pragma unroll
    for (int i = 0; i < 4; i++)
        #pragma unroll
        for (int j = 0; j < 4; j++)
            #pragma unroll
            for (int k = 0; k < 4; k++) acc[i][j][k] = 0.f;

    const int m0 = blockIdx.y * 128;
    const int n0 = blockIdx.x * 128;
    gemm_f16_mainloop(X + (size_t)m0 * DM, W + (size_t)n0 * DM, DM, smem, acc);

    const int tid = threadIdx.x;
    const int lane = tid & 31;
    const int wid = tid >> 5;
    const int g = lane >> 2, c = lane & 3;
    const int mwarp = wid >> 2, nwarp = wid & 3;

    const int comp = n0 >> 11;            // 0=Q, 1=K, 2=V
    const int h = (n0 >> 7) & 15;
    unsigned short* dhi = (comp == 0) ? g_Qhi : (comp == 1) ? g_Khi : g_Vhi;
    unsigned short* dlo = (comp == 0) ? g_Qlo : (comp == 1) ? g_Klo : g_Vlo;

    #pragma unroll
    for (int mt = 0; mt < 4; mt++) {
        #pragma unroll
        for (int rr = 0; rr < 2; rr++) {
            int m = m0 + mwarp * 64 + mt * 16 + g + rr * 8;
            int bb = m >> 11, s = m & 2047;
            size_t base = ((size_t)(bb * NH + h) * SEQ + s) * HD;
            #pragma unroll
            for (int ntp = 0; ntp < 2; ntp++) {
                int d0 = nwarp * 16 + ntp * 8 + 2 * c;       // 0..63
                float v0e0 = acc[mt][ntp][rr * 2]     + bias[n0 + d0];
                float v0e1 = acc[mt][ntp][rr * 2 + 1] + bias[n0 + d0 + 1];
                float v1e0 = acc[mt][ntp + 2][rr * 2]     + bias[n0 + 64 + d0];
                float v1e1 = acc[mt][ntp + 2][rr * 2 + 1] + bias[n0 + 64 + d0 + 1];
                unsigned int hi, lo;
                if (comp == 2) {
                    split2(v0e0, v0e1, hi, lo);
                    *(unsigned int*)&dhi[base + d0] = hi;
                    *(unsigned int*)&dlo[base + d0] = lo;
                    split2(v1e0, v1e1, hi, lo);
                    *(unsigned int*)&dhi[base + 64 + d0] = hi;
                    *(unsigned int*)&dlo[base + 64 + d0] = lo;
                } else {
                    float2 cs = *(const float2*)&g_cos[s * 64 + d0];
                    float2 sn = *(const float2*)&g_sin[s * 64 + d0];
                    float q0e0 = v0e0 * cs.x - v1e0 * sn.x;
                    float q0e1 = v0e1 * cs.y - v1e1 * sn.y;
                    float q1e0 = v1e0 * cs.x + v0e0 * sn.x;
                    float q1e1 = v1e1 * cs.y + v0e1 * sn.y;
                    split2(q0e0, q0e1, hi, lo);
                    *(unsigned int*)&dhi[base + d0] = hi;
                    *(unsigned int*)&dlo[base + d0] = lo;
                    split2(q1e0, q1e1, hi, lo);
                    *(unsigned int*)&dhi[base + 64 + d0] = hi;
                    *(unsigned int*)&dlo[base + 64 + d0] = lo;
                }
            }
        }
    }
}

// ---------------- output projection GEMM (reads g_ctx) ----------------------
__global__ void __launch_bounds__(GEMM_NTHREADS, 2) out_gemm_kernel(
    const float* __restrict__ W, const float* __restrict__ bias,
    float* __restrict__ C)
{
    extern __shared__ __align__(16) char smem[];
    float acc[4][4][4];
    #pragma unroll
    for (int i = 0; i < 4; i++)
        #pragma unroll
        for (int j = 0; j < 4; j++)
            #pragma unroll
            for (int k = 0; k < 4; k++) acc[i][j][k] = 0.f;

    const int m0 = blockIdx.y * 128;
    const int n0 = blockIdx.x * 128;
    gemm_f16_mainloop(g_ctx + (size_t)m0 * DM, W + (size_t)n0 * DM, DM, smem, acc);

    const int tid = threadIdx.x;
    const int lane = tid & 31;
    const int wid = tid >> 5;
    const int g = lane >> 2, c = lane & 3;
    const int mwarp = wid >> 2, nwarp = wid & 3;

    #pragma unroll
    for (int mt = 0; mt < 4; mt++) {
        #pragma unroll
        for (int rr = 0; rr < 2; rr++) {
            int row = m0 + mwarp * 64 + mt * 16 + g + rr * 8;
            #pragma unroll
            for (int nt = 0; nt < 4; nt++) {
                int colb = n0 + nwarp * 16 + (nt & 1) * 8 + (nt >> 1) * 64 + 2 * c;
                float2 st;
                st.x = acc[mt][nt][rr * 2]     + bias[colb];
                st.y = acc[mt][nt][rr * 2 + 1] + bias[colb + 1];
                *(float2*)(C + (size_t)row * DM + colb) = st;
            }
        }
    }
}

// ---------------- tensor-core flash attention (bf16 split-3) ----------------
// Inputs pre-split in gmem (hi/lo ushort). BM=128, BN=64, D=128.
#define QSTR 136   // Q/K smem row stride (bf16 elems)
#define VSTR 72    // Vt/P smem row stride
#define SM_QHI 0
#define SM_QLO (SM_QHI + 128*QSTR)
#define SM_KHI (SM_QLO + 128*QSTR)
#define SM_KLO (SM_KHI + 64*QSTR)
#define SM_VHI (SM_KLO + 64*QSTR)
#define SM_VLO (SM_VHI + 128*VSTR)
#define SM_PHI (SM_VLO + 128*VSTR)
#define SM_PLO (SM_PHI + 128*VSTR)
#define SM_ATTN_ELEMS (SM_PLO + 128*VSTR)

__global__ void __launch_bounds__(256) attn_mma_kernel() {
    extern __shared__ __align__(16) unsigned short sm[];
    unsigned short* Qhi = sm + SM_QHI;
    unsigned short* Qlo = sm + SM_QLO;
    unsigned short* Khi = sm + SM_KHI;
    unsigned short* Klo = sm + SM_KLO;
    unsigned short* Vhi = sm + SM_VHI;   // transposed: [d][s], stride VSTR
    unsigned short* Vlo = sm + SM_VLO;
    unsigned short* Phi = sm + SM_PHI;
    unsigned short* Plo = sm + SM_PLO;

    const int tid = threadIdx.x;
    const int lane = tid & 31;
    const int wid = tid >> 5;
    const int g = lane >> 2;           // 0..7
    const int c = lane & 3;            // 0..3
    const int m0 = wid * 16;
    const int qb = blockIdx.x;         // 0..15
    const int bh = blockIdx.y;         // 0..31
    const int b = bh >> 4, h = bh & 15;

    const size_t bhoff = (size_t)bh * SEQ * HD;
    const unsigned short* Qg_hi = g_Qhi + bhoff + (size_t)qb * 128 * HD;
    const unsigned short* Qg_lo = g_Qlo + bhoff + (size_t)qb * 128 * HD;
    const unsigned short* Kg_hi0 = g_Khi + bhoff;
    const unsigned short* Kg_lo0 = g_Klo + bhoff;
    const unsigned short* Vg_hi0 = g_Vhi + bhoff;
    const unsigned short* Vg_lo0 = g_Vlo + bhoff;

    // ---- load Q (128x128 hi+lo, straight copy) ----
    #pragma unroll
    for (int it = 0; it < 16; it++) {
        int idx = tid + it * 256;                 // 0..4095
        const unsigned short* src = (it < 8) ? Qg_hi : Qg_lo;
        unsigned short* dst = (it < 8) ? Qhi : Qlo;
        int rem = idx & 2047;
        int row = rem >> 4, d = (rem & 15) * 8;
        *(uint4*)&dst[row * QSTR + d] = *(const uint4*)&src[row * HD + d];
    }

    float o[16][4];
    float mrow[2], lrow[2];
    #pragma unroll
    for (int i = 0; i < 16; i++)
        #pragma unroll
        for (int j = 0; j < 4; j++) o[i][j] = 0.f;
    mrow[0] = mrow[1] = -1e30f;
    lrow[0] = lrow[1] = 0.f;

    const int r0 = qb * 128 + m0 + g;
    const int r1 = r0 + 8;

    const int kbmax = 2 * qb + 1;
    for (int kb = 0; kb <= kbmax; kb++) {
        __syncthreads();
        const size_t koff = (size_t)kb * 64 * HD;

        // K tile [64][128] hi+lo: straight copy
        #pragma unroll
        for (int it = 0; it < 8; it++) {
            int idx = tid + it * 256;             // 0..2047
            const unsigned short* src = (it < 4) ? Kg_hi0 : Kg_lo0;
            unsigned short* dst = (it < 4) ? Khi : Klo;
            int rem = idx & 1023;
            int row = rem >> 4, d = (rem & 15) * 8;
            *(uint4*)&dst[row * QSTR + d] = *(const uint4*)&src[koff + row * HD + d];
        }
        // V tile: transpose to [d][s-pairs] via byte_perm
        #pragma unroll
        for (int it = 0; it < 4; it++) {
            int idx = tid + it * 256;             // 0..1023
            const unsigned short* src = (it < 2) ? Vg_hi0 : Vg_lo0;
            unsigned short* dst = (it < 2) ? Vhi : Vlo;
            int rem = idx & 511;
            int s = (rem >> 4) * 2;
            int d = (rem & 15) * 8;
            uint4 ua = *(const uint4*)&src[koff + (size_t)s * HD + d];
            uint4 ub = *(const uint4*)&src[koff + (size_t)(s + 1) * HD + d];
            unsigned int uav[4] = {ua.x, ua.y, ua.z, ua.w};
            unsigned int ubv[4] = {ub.x, ub.y, ub.z, ub.w};
            #pragma unroll
            for (int j = 0; j < 4; j++) {
                unsigned int plo = __byte_perm(uav[j], ubv[j], 0x5410);
                unsigned int phi = __byte_perm(uav[j], ubv[j], 0x7632);
                *(unsigned int*)&dst[(d + 2 * j) * VSTR + s]     = plo;
                *(unsigned int*)&dst[(d + 2 * j + 1) * VSTR + s] = phi;
            }
        }
        __syncthreads();

        // ---- S = Q @ K^T ----
        float sacc[8][4];
        #pragma unroll
        for (int nt = 0; nt < 8; nt++)
            #pragma unroll
            for (int e = 0; e < 4; e++) sacc[nt][e] = 0.f;

        #pragma unroll
        for (int ks = 0; ks < 8; ks++) {
            const int k0 = ks * 16;
            unsigned int ah[4], al[4];
            ah[0] = *(unsigned int*)&Qhi[(m0 + g) * QSTR + k0 + 2 * c];
            ah[1] = *(unsigned int*)&Qhi[(m0 + g + 8) * QSTR + k0 + 2 * c];
            ah[2] = *(unsigned int*)&Qhi[(m0 + g) * QSTR + k0 + 2 * c + 8];
            ah[3] = *(unsigned int*)&Qhi[(m0 + g + 8) * QSTR + k0 + 2 * c + 8];
            al[0] = *(unsigned int*)&Qlo[(m0 + g) * QSTR + k0 + 2 * c];
            al[1] = *(unsigned int*)&Qlo[(m0 + g + 8) * QSTR + k0 + 2 * c];
            al[2] = *(unsigned int*)&Qlo[(m0 + g) * QSTR + k0 + 2 * c + 8];
            al[3] = *(unsigned int*)&Qlo[(m0 + g + 8) * QSTR + k0 + 2 * c + 8];
            #pragma unroll
            for (int nt = 0; nt < 8; nt++) {
                unsigned int bh0 = *(unsigned int*)&Khi[(nt * 8 + g) * QSTR + k0 + 2 * c];
                unsigned int bh1 = *(unsigned int*)&Khi[(nt * 8 + g) * QSTR + k0 + 2 * c + 8];
                unsigned int bl0 = *(unsigned int*)&Klo[(nt * 8 + g) * QSTR + k0 + 2 * c];
                unsigned int bl1 = *(unsigned int*)&Klo[(nt * 8 + g) * QSTR + k0 + 2 * c + 8];
                mma_bf16(sacc[nt], ah, bh0, bh1);
                mma_bf16(sacc[nt], al, bh0, bh1);
                mma_bf16(sacc[nt], ah, bl0, bl1);
            }
        }

        // ---- scale + causal mask + online softmax ----
        float smax0 = -1e30f, smax1 = -1e30f;
        #pragma unroll
        for (int nt = 0; nt < 8; nt++) {
            int col = kb * 64 + nt * 8 + 2 * c;
            float v00 = sacc[nt][0] * SCALE; if (col     > r0) v00 = -1e30f;
            float v01 = sacc[nt][1] * SCALE; if (col + 1 > r0) v01 = -1e30f;
            float v10 = sacc[nt][2] * SCALE; if (col     > r1) v10 = -1e30f;
            float v11 = sacc[nt][3] * SCALE; if (col + 1 > r1) v11 = -1e30f;
            sacc[nt][0] = v00; sacc[nt][1] = v01;
            sacc[nt][2] = v10; sacc[nt][3] = v11;
            smax0 = fmaxf(smax0, fmaxf(v00, v01));
            smax1 = fmaxf(smax1, fmaxf(v10, v11));
        }
        smax0 = fmaxf(smax0, __shfl_xor_sync(0xffffffffu, smax0, 1));
        smax0 = fmaxf(smax0, __shfl_xor_sync(0xffffffffu, smax0, 2));
        smax1 = fmaxf(smax1, __shfl_xor_sync(0xffffffffu, smax1, 1));
        smax1 = fmaxf(smax1, __shfl_xor_sync(0xffffffffu, smax1, 2));

        float mnew0 = fmaxf(mrow[0], smax0);
        float mnew1 = fmaxf(mrow[1], smax1);
        float corr0 = __expf(mrow[0] - mnew0);
        float corr1 = __expf(mrow[1] - mnew1);
        mrow[0] = mnew0; mrow[1] = mnew1;

        float rsum0 = 0.f, rsum1 = 0.f;
        #pragma unroll
        for (int nt = 0; nt < 8; nt++) {
            float p00 = __expf(sacc[nt][0] - mnew0);
            float p01 = __expf(sacc[nt][1] - mnew0);
            float p10 = __expf(sacc[nt][2] - mnew1);
            float p11 = __expf(sacc[nt][3] - mnew1);
            rsum0 += p00 + p01;
            rsum1 += p10 + p11;
            unsigned int hi, lo;
            split2(p00, p01, hi, lo);
            *(unsigned int*)&Phi[(m0 + g) * VSTR + nt * 8 + 2 * c] = hi;
            *(unsigned int*)&Plo[(m0 + g) * VSTR + nt * 8 + 2 * c] = lo;
            split2(p10, p11, hi, lo);
            *(unsigned int*)&Phi[(m0 + g + 8) * VSTR + nt * 8 + 2 * c] = hi;
            *(unsigned int*)&Plo[(m0 + g + 8) * VSTR + nt * 8 + 2 * c] = lo;
        }
        rsum0 += __shfl_xor_sync(0xffffffffu, rsum0, 1);
        rsum0 += __shfl_xor_sync(0xffffffffu, rsum0, 2);
        rsum1 += __shfl_xor_sync(0xffffffffu, rsum1, 1);
        rsum1 += __shfl_xor_sync(0xffffffffu, rsum1, 2);
        lrow[0] = lrow[0] * corr0 + rsum0;
        lrow[1] = lrow[1] * corr1 + rsum1;

        #pragma unroll
        for (int nt = 0; nt < 16; nt++) {
            o[nt][0] *= corr0; o[nt][1] *= corr0;
            o[nt][2] *= corr1; o[nt][3] *= corr1;
        }

        // ---- O += P @ V ----
        #pragma unroll
        for (int ks = 0; ks < 4; ks++) {
            const int k0 = ks * 16;
            unsigned int ah[4], al[4];
            ah[0] = *(unsigned int*)&Phi[(m0 + g) * VSTR + k0 + 2 * c];
            ah[1] = *(unsigned int*)&Phi[(m0 + g + 8) * VSTR + k0 + 2 * c];
            ah[2] = *(unsigned int*)&Phi[(m0 + g) * VSTR + k0 + 2 * c + 8];
            ah[3] = *(unsigned int*)&Phi[(m0 + g + 8) * VSTR + k0 + 2 * c + 8];
            al[0] = *(unsigned int*)&Plo[(m0 + g) * VSTR + k0 + 2 * c];
            al[1] = *(unsigned int*)&Plo[(m0 + g + 8) * VSTR + k0 + 2 * c];
            al[2] = *(unsigned int*)&Plo[(m0 + g) * VSTR + k0 + 2 * c + 8];
            al[3] = *(unsigned int*)&Plo[(m0 + g + 8) * VSTR + k0 + 2 * c + 8];
            #pragma unroll
            for (int nt = 0; nt < 16; nt++) {
                unsigned int bh0 = *(unsigned int*)&Vhi[(nt * 8 + g) * VSTR + k0 + 2 * c];
                unsigned int bh1 = *(unsigned int*)&Vhi[(nt * 8 + g) * VSTR + k0 + 2 * c + 8];
                unsigned int bl0 = *(unsigned int*)&Vlo[(nt * 8 + g) * VSTR + k0 + 2 * c];
                unsigned int bl1 = *(unsigned int*)&Vlo[(nt * 8 + g) * VSTR + k0 + 2 * c + 8];
                mma_bf16(o[nt], ah, bh0, bh1);
                mma_bf16(o[nt], al, bh0, bh1);
                mma_bf16(o[nt], ah, bl0, bl1);
            }
        }
    }

    // ---- normalize + write ctx ----
    float inv0 = 1.0f / lrow[0];
    float inv1 = 1.0f / lrow[1];
    int s0 = qb * 128 + m0 + g;
    size_t base0 = ((size_t)b * SEQ + s0) * DM + h * HD;
    size_t base1 = ((size_t)b * SEQ + s0 + 8) * DM + h * HD;
    #pragma unroll
    for (int nt = 0; nt < 16; nt++) {
        int d0 = nt * 8 + 2 * c;
        float2 w0 = {o[nt][0] * inv0, o[nt][1] * inv0};
        float2 w1 = {o[nt][2] * inv1, o[nt][3] * inv1};
        *(float2*)(g_ctx + base0 + d0) = w0;
        *(float2*)(g_ctx + base1 + d0) = w1;
    }
}

// ---------------- launch ----------------------------------------------------
extern "C" void kernel_launch(void* const* d_in, const int* in_sizes, int n_in,
                              void* d_out, int out_size) {
    const float* x      = (const float*)d_in[0];
    // d_in[1] = attn_mask (causal, recomputed on the fly; unused)
    const float* Wqkv_w = (const float*)d_in[2];
    const float* Wqkv_b = (const float*)d_in[3];
    const float* out_w  = (const float*)d_in[4];
    const float* out_b  = (const float*)d_in[5];
    float* out = (float*)d_out;

    build_rope_kernel<<<(SEQ * 64 + 255) / 256, 256>>>();

    cudaFuncSetAttribute(qkv_gemm_kernel,
                         cudaFuncAttributeMaxDynamicSharedMemorySize, GEMM_SMEM_BYTES);
    cudaFuncSetAttribute(out_gemm_kernel,
                         cudaFuncAttributeMaxDynamicSharedMemorySize, GEMM_SMEM_BYTES);

    qkv_gemm_kernel<<<dim3(NQKV / 128, MROWS / 128), GEMM_NTHREADS,
                      GEMM_SMEM_BYTES>>>(x, Wqkv_w, Wqkv_b);

    const int ATTN_SMEM = SM_ATTN_ELEMS * 2;
    cudaFuncSetAttribute(attn_mma_kernel,
                         cudaFuncAttributeMaxDynamicSharedMemorySize, ATTN_SMEM);
    attn_mma_kernel<<<dim3(SEQ / 128, BATCH * NH), 256, ATTN_SMEM>>>();

    out_gemm_kernel<<<dim3(DM / 128, MROWS / 128), GEMM_NTHREADS,
                      GEMM_SMEM_BYTES>>>(out_w, out_b, out);
}

// round 14
// speedup vs baseline: 1.5801x; 1.2658x over previous
#include <cuda_runtime.h>
#include <cuda_bf16.h>
#include <cuda_fp16.h>
#include <cstdint>
#include <stdint.h>
#include <math.h>

#define BATCH 2
#define SEQ 2048
#define NH 16
#define HD 128
#define DM 2048
#define MROWS (BATCH*SEQ)     // 4096
#define NQKV (3*DM)           // 6144
#define SCALE 0.08838834764831845f  // 1/sqrt(128)

// ---------------- scratch (static device globals: allocation-free) ----------
__device__ unsigned short g_Qhi[BATCH*NH*SEQ*HD];
__device__ unsigned short g_Qlo[BATCH*NH*SEQ*HD];
__device__ unsigned short g_Khi[BATCH*NH*SEQ*HD];
__device__ unsigned short g_Klo[BATCH*NH*SEQ*HD];
__device__ unsigned short g_Vhi[BATCH*NH*SEQ*HD];
__device__ unsigned short g_Vlo[BATCH*NH*SEQ*HD];
__device__ float g_ctx[MROWS*DM];        // [b*s, h*d]
__device__ float g_cos[SEQ*64];
__device__ float g_sin[SEQ*64];

// ---------------- RoPE table -------------------------------------------------
__global__ void build_rope_kernel() {
    int idx = blockIdx.x * blockDim.x + threadIdx.x;
    if (idx >= SEQ * 64) return;
    int pos = idx >> 6, i = idx & 63;
    double f = pow(10000.0, -(double)i / 64.0);
    double a = (double)pos * f;
    g_cos[idx] = (float)cos(a);
    g_sin[idx] = (float)sin(a);
}

// ---------------- fp16 / bf16 helpers ----------------------------------------
__device__ __forceinline__ unsigned f2h2(float lo, float hi) {
    __half2 h = __floats2half2_rn(lo, hi);
    return *(unsigned*)&h;
}

__device__ __forceinline__ void mma_f16(float (&cacc)[4],
                                        const uint4 &a,
                                        unsigned b0, unsigned b1) {
    asm volatile(
        "mma.sync.aligned.m16n8k16.row.col.f32.f16.f16.f32 "
        "{%0,%1,%2,%3}, {%4,%5,%6,%7}, {%8,%9}, {%0,%1,%2,%3};\n"
        : "+f"(cacc[0]), "+f"(cacc[1]), "+f"(cacc[2]), "+f"(cacc[3])
        : "r"(a.x), "r"(a.y), "r"(a.z), "r"(a.w), "r"(b0), "r"(b1));
}

__device__ __forceinline__ void mma_bf16(float (&cacc)[4],
                                         const unsigned int (&a)[4],
                                         unsigned int b0, unsigned int b1) {
    asm volatile(
        "mma.sync.aligned.m16n8k16.row.col.f32.bf16.bf16.f32 "
        "{%0,%1,%2,%3}, {%4,%5,%6,%7}, {%8,%9}, {%0,%1,%2,%3};\n"
        : "+f"(cacc[0]), "+f"(cacc[1]), "+f"(cacc[2]), "+f"(cacc[3])
        : "r"(a[0]), "r"(a[1]), "r"(a[2]), "r"(a[3]), "r"(b0), "r"(b1));
}

// split two floats into packed bf16 hi pair + bf16 residual-lo pair
__device__ __forceinline__ void split2(float a, float b,
                                       unsigned int &hi, unsigned int &lo) {
    __nv_bfloat16 ha = __float2bfloat16(a);
    __nv_bfloat16 hb = __float2bfloat16(b);
    float ra = a - __bfloat162float(ha);
    float rb = b - __bfloat162float(hb);
    __nv_bfloat16 la = __float2bfloat16(ra);
    __nv_bfloat16 lb = __float2bfloat16(rb);
    hi = (unsigned int)__bfloat16_as_ushort(ha) |
         ((unsigned int)__bfloat16_as_ushort(hb) << 16);
    lo = (unsigned int)__bfloat16_as_ushort(la) |
         ((unsigned int)__bfloat16_as_ushort(lb) << 16);
}

// ---------------- ldmatrix / cp.async helpers --------------------------------
#define LDSM_X4(r0, r1, r2, r3, addr) \
    asm volatile("ldmatrix.sync.aligned.m8n8.x4.shared.b16 {%0,%1,%2,%3}, [%4];" \
        : "=r"(r0), "=r"(r1), "=r"(r2), "=r"(r3) : "r"(addr))

#define LDSM_X4_T(r0, r1, r2, r3, addr) \
    asm volatile("ldmatrix.sync.aligned.m8n8.x4.trans.shared.b16 {%0,%1,%2,%3}, [%4];" \
        : "=r"(r0), "=r"(r1), "=r"(r2), "=r"(r3) : "r"(addr))

#define CP_ASYNC16(dst_u32, src_ptr) \
    asm volatile("cp.async.cg.shared.global [%0], [%1], 16;" \
        :: "r"(dst_u32), "l"(src_ptr) : "memory")

#define CP_COMMIT() asm volatile("cp.async.commit_group;" ::: "memory")
#define CP_WAIT_ALL() asm volatile("cp.async.wait_group 0;" ::: "memory")

__device__ __forceinline__ uint32_t smem_u32_of(const void* p) {
    uint32_t a;
    asm("{ .reg .u64 t; cvta.to.shared.u64 t, %1; cvt.u32.u64 %0, t; }"
        : "=r"(a) : "l"(p));
    return a;
}

// ---------------- fp16 HMMA 128x128xK NT GEMM mainloop (round-13) -----------
#define GEMM_NTHREADS 256
#define ASF_BYTES (2*8*33*16)                 // 8448
#define BSF_BYTES (2*16*33*8)                 // 4224
#define GEMM_SMEM_BYTES (ASF_BYTES + BSF_BYTES)   // 12672

__device__ __forceinline__ void gemm_f16_mainloop(
    const float* __restrict__ Ag, const float* __restrict__ Bg,
    int K, char* smem, float (&acc)[4][4][4])
{
    uint4* Asf = (uint4*)smem;                    // [2][8][33]
    uint2* Bsf = (uint2*)(smem + ASF_BYTES);      // [2][16][33]
    unsigned* Asu = (unsigned*)smem;
    unsigned* Bsu = (unsigned*)(smem + ASF_BYTES);

    const int tid = threadIdx.x;
    const int lane = tid & 31;
    const int wid = tid >> 5;
    const int mwarp = wid >> 2;
    const int nwarp = wid & 3;
    const int r0 = tid >> 2;
    const int kc0 = (tid & 3) * 4;
    const int KT = K >> 4;

    const int c0 = (kc0 >> 1) & 3;
    const int kh = kc0 >> 3;
    const int mtA0 = r0 >> 4;
    const int gA = r0 & 7;
    const int regA = ((r0 >> 3) & 1) + 2 * kh;
    const int idxA0 = (mtA0 * 33 + gA * 4 + c0) * 4 + regA;
    const int idxA1 = ((mtA0 + 4) * 33 + gA * 4 + c0) * 4 + regA;
    int idxB[2];
    #pragma unroll
    for (int j = 0; j < 2; j++) {
        int nr = r0 + 64 * j;
        int rem = nr & 63;
        int nwS = rem >> 4;
        int e8 = (rem >> 3) & 1;
        int gcol = rem & 7;
        int nt = j * 2 + e8;
        int nb = nwS * 4 + nt;
        idxB[j] = (nb * 33 + gcol * 4 + c0) * 2 + kh;
    }

    float4 pa0, pa1, pb0, pb1;
    pa0 = *(const float4*)(Ag + (size_t)r0 * K + kc0);
    pa1 = *(const float4*)(Ag + (size_t)(r0 + 64) * K + kc0);
    pb0 = *(const float4*)(Bg + (size_t)r0 * K + kc0);
    pb1 = *(const float4*)(Bg + (size_t)(r0 + 64) * K + kc0);

    const int abufu = 8 * 33 * 4;
    const int bbufu = 16 * 33 * 2;

    for (int kb = 0; kb < KT; kb++) {
        const int buf = kb & 1;
        {
            int ao = buf * abufu;
            Asu[ao + idxA0]     = f2h2(pa0.x, pa0.y);
            Asu[ao + idxA0 + 4] = f2h2(pa0.z, pa0.w);
            Asu[ao + idxA1]     = f2h2(pa1.x, pa1.y);
            Asu[ao + idxA1 + 4] = f2h2(pa1.z, pa1.w);
            int bo = buf * bbufu;
            Bsu[bo + idxB[0]]     = f2h2(pb0.x, pb0.y);
            Bsu[bo + idxB[0] + 2] = f2h2(pb0.z, pb0.w);
            Bsu[bo + idxB[1]]     = f2h2(pb1.x, pb1.y);
            Bsu[bo + idxB[1] + 2] = f2h2(pb1.z, pb1.w);
        }
        __syncthreads();

        if (kb + 1 < KT) {
            int ko = (kb + 1) * 16 + kc0;
            pa0 = *(const float4*)(Ag + (size_t)r0 * K + ko);
            pa1 = *(const float4*)(Ag + (size_t)(r0 + 64) * K + ko);
            pb0 = *(const float4*)(Bg + (size_t)r0 * K + ko);
            pb1 = *(const float4*)(Bg + (size_t)(r0 + 64) * K + ko);
        }

        {
            uint4 a4[4];
            uint2 b2[4];
            #pragma unroll
            for (int mt = 0; mt < 4; mt++)
                a4[mt] = Asf[(buf * 8 + mwarp * 4 + mt) * 33 + lane];
            #pragma unroll
            for (int nt = 0; nt < 4; nt++)
                b2[nt] = Bsf[(buf * 16 + nwarp * 4 + nt) * 33 + lane];
            #pragma unroll
            for (int mt = 0; mt < 4; mt++)
                #pragma unroll
                for (int nt = 0; nt < 4; nt++)
                    mma_f16(acc[mt][nt], a4[mt], b2[nt].x, b2[nt].y);
        }
    }
}

// ---------------- QKV GEMM with fused bias + RoPE + bf16-split scatter ------
__global__ void __launch_bounds__(GEMM_NTHREADS, 2) qkv_gemm_kernel(
    const float* __restrict__ X, const float* __restrict__ W,
    const float* __restrict__ bias)
{
    extern __shared__ __align__(16) char smem[];
    float acc[4][4][4];
    #pragma unroll
    for (int i = 0; i < 4; i++)
        #pragma unroll
        for (int j = 0; j < 4; j++)
            #pragma unroll
            for (int k = 0; k < 4; k++) acc[i][j][k] = 0.f;

    const int m0 = blockIdx.y * 128;
    const int n0 = blockIdx.x * 128;
    gemm_f16_mainloop(X + (size_t)m0 * DM, W + (size_t)n0 * DM, DM, smem, acc);

    const int tid = threadIdx.x;
    const int lane = tid & 31;
    const int wid = tid >> 5;
    const int g = lane >> 2, c = lane & 3;
    const int mwarp = wid >> 2, nwarp = wid & 3;

    const int comp = n0 >> 11;            // 0=Q, 1=K, 2=V
    const int h = (n0 >> 7) & 15;
    unsigned short* dhi = (comp == 0) ? g_Qhi : (comp == 1) ? g_Khi : g_Vhi;
    unsigned short* dlo = (comp == 0) ? g_Qlo : (comp == 1) ? g_Klo : g_Vlo;

    #pragma unroll
    for (int mt = 0; mt < 4; mt++) {
        #pragma unroll
        for (int rr = 0; rr < 2; rr++) {
            int m = m0 + mwarp * 64 + mt * 16 + g + rr * 8;
            int bb = m >> 11, s = m & 2047;
            size_t base = ((size_t)(bb * NH + h) * SEQ + s) * HD;
            #pragma unroll
            for (int ntp = 0; ntp < 2; ntp++) {
                int d0 = nwarp * 16 + ntp * 8 + 2 * c;       // 0..63
                float v0e0 = acc[mt][ntp][rr * 2]     + bias[n0 + d0];
                float v0e1 = acc[mt][ntp][rr * 2 + 1] + bias[n0 + d0 + 1];
                float v1e0 = acc[mt][ntp + 2][rr * 2]     + bias[n0 + 64 + d0];
                float v1e1 = acc[mt][ntp + 2][rr * 2 + 1] + bias[n0 + 64 + d0 + 1];
                unsigned int hi, lo;
                if (comp == 2) {
                    split2(v0e0, v0e1, hi, lo);
                    *(unsigned int*)&dhi[base + d0] = hi;
                    *(unsigned int*)&dlo[base + d0] = lo;
                    split2(v1e0, v1e1, hi, lo);
                    *(unsigned int*)&dhi[base + 64 + d0] = hi;
                    *(unsigned int*)&dlo[base + 64 + d0] = lo;
                } else {
                    float2 cs = *(const float2*)&g_cos[s * 64 + d0];
                    float2 sn = *(const float2*)&g_sin[s * 64 + d0];
                    float q0e0 = v0e0 * cs.x - v1e0 * sn.x;
                    float q0e1 = v0e1 * cs.y - v1e1 * sn.y;
                    float q1e0 = v1e0 * cs.x + v0e0 * sn.x;
                    float q1e1 = v1e1 * cs.y + v0e1 * sn.y;
                    split2(q0e0, q0e1, hi, lo);
                    *(unsigned int*)&dhi[base + d0] = hi;
                    *(unsigned int*)&dlo[base + d0] = lo;
                    split2(q1e0, q1e1, hi, lo);
                    *(unsigned int*)&dhi[base + 64 + d0] = hi;
                    *(unsigned int*)&dlo[base + 64 + d0] = lo;
                }
            }
        }
    }
}

// ---------------- output projection GEMM (reads g_ctx) ----------------------
__global__ void __launch_bounds__(GEMM_NTHREADS, 2) out_gemm_kernel(
    const float* __restrict__ W, const float* __restrict__ bias,
    float* __restrict__ C)
{
    extern __shared__ __align__(16) char smem[];
    float acc[4][4][4];
    #pragma unroll
    for (int i = 0; i < 4; i++)
        #pragma unroll
        for (int j = 0; j < 4; j++)
            #pragma unroll
            for (int k = 0; k < 4; k++) acc[i][j][k] = 0.f;

    const int m0 = blockIdx.y * 128;
    const int n0 = blockIdx.x * 128;
    gemm_f16_mainloop(g_ctx + (size_t)m0 * DM, W + (size_t)n0 * DM, DM, smem, acc);

    const int tid = threadIdx.x;
    const int lane = tid & 31;
    const int wid = tid >> 5;
    const int g = lane >> 2, c = lane & 3;
    const int mwarp = wid >> 2, nwarp = wid & 3;

    #pragma unroll
    for (int mt = 0; mt < 4; mt++) {
        #pragma unroll
        for (int rr = 0; rr < 2; rr++) {
            int row = m0 + mwarp * 64 + mt * 16 + g + rr * 8;
            #pragma unroll
            for (int nt = 0; nt < 4; nt++) {
                int colb = n0 + nwarp * 16 + (nt & 1) * 8 + (nt >> 1) * 64 + 2 * c;
                float2 st;
                st.x = acc[mt][nt][rr * 2]     + bias[colb];
                st.y = acc[mt][nt][rr * 2 + 1] + bias[colb + 1];
                *(float2*)(C + (size_t)row * DM + colb) = st;
            }
        }
    }
}

// ---------------- flash attention: ldmatrix + cp.async + register-P ---------
// BM=128, BN=64, D=128. Q/K/V row-major [rows][ASTR] bf16 hi/lo in smem.
// K/V double-buffered via cp.async (tile kb+1 in flight under compute of kb).
// P stays in registers: S-frag ownership == PV A-frag requirement.
#define ASTR 136
#define SM_QHI 0
#define SM_QLO (128*ASTR)              // 17408 ushorts
#define SM_KV  (2*128*ASTR)            // 34816
#define KV_BUF (4*64*ASTR)             // 34816 ushorts per buffer
#define ATTN_SMEM_BYTES ((SM_KV + 2*KV_BUF) * 2)   // 208896

__global__ void __launch_bounds__(256) attn_mma_kernel() {
    extern __shared__ __align__(16) unsigned short sm[];
    const uint32_t smb = smem_u32_of(sm);

    const int tid = threadIdx.x;
    const int lane = tid & 31;
    const int wid = tid >> 5;
    const int g = lane >> 2;           // 0..7
    const int c = lane & 3;            // 0..3
    const int m0 = wid * 16;
    const int qb = blockIdx.x;         // 0..15
    const int bh = blockIdx.y;         // 0..31
    const int b = bh >> 4, h = bh & 15;

    const size_t bhoff = (size_t)bh * SEQ * HD;
    const unsigned short* Qg_hi = g_Qhi + bhoff + (size_t)qb * 128 * HD;
    const unsigned short* Qg_lo = g_Qlo + bhoff + (size_t)qb * 128 * HD;
    const unsigned short* Kg_hi0 = g_Khi + bhoff;
    const unsigned short* Kg_lo0 = g_Klo + bhoff;
    const unsigned short* Vg_hi0 = g_Vhi + bhoff;
    const unsigned short* Vg_lo0 = g_Vlo + bhoff;

    // ---- load Q (128x128 hi+lo, straight copy) ----
    #pragma unroll
    for (int it = 0; it < 16; it++) {
        int idx = tid + it * 256;                 // 0..4095
        const unsigned short* src = (it < 8) ? Qg_hi : Qg_lo;
        unsigned short* dst = (it < 8) ? (sm + SM_QHI) : (sm + SM_QLO);
        int rem = idx & 2047;
        int row = rem >> 4, d = (rem & 15) * 8;
        *(uint4*)&dst[row * ASTR + d] = *(const uint4*)&src[row * HD + d];
    }

    // lane-constant ldmatrix offsets (bytes)
    const int lrow = lane & 7;
    const int lj = lane >> 3;          // 0..3
    // A-frag (Q, m16k16): r_j: row += (j&1)*8, col += (j>>1)*8
    const uint32_t qA_off = (uint32_t)(((m0 + lrow + (lj & 1) * 8) * ASTR +
                                        (lj >> 1) * 8) * 2);
    const uint32_t qhiA = smb + SM_QHI * 2 + qA_off;
    const uint32_t qloA = smb + SM_QLO * 2 + qA_off;
    // B-frag (K, n8k16 pairs): r_j: row += (j>>1)*8, col += (j&1)*8
    const uint32_t kB_off = (uint32_t)(((lrow + (lj >> 1) * 8) * ASTR +
                                        (lj & 1) * 8) * 2);
    // B-frag (V, trans): r_j: s-row += (j&1)*8, d-col += (j>>1)*8
    const uint32_t vB_off = (uint32_t)(((lrow + (lj & 1) * 8) * ASTR +
                                        (lj >> 1) * 8) * 2);

    float o[16][4];
    float mrow[2], lrow2[2];
    #pragma unroll
    for (int i = 0; i < 16; i++)
        #pragma unroll
        for (int j = 0; j < 4; j++) o[i][j] = 0.f;
    mrow[0] = mrow[1] = -1e30f;
    lrow2[0] = lrow2[1] = 0.f;

    const int r0 = qb * 128 + m0 + g;
    const int r1 = r0 + 8;
    const int kbmax = 2 * qb + 1;

    // issue cp.async K/V tile into buffer
    auto issue_kv = [&](int buf, int kb) {
        const size_t koff = (size_t)kb * 64 * HD;
        const uint32_t base = smb + (uint32_t)(SM_KV + buf * KV_BUF) * 2;
        #pragma unroll
        for (int it = 0; it < 4; it++) {
            int chunk = tid + it * 256;           // 0..1023
            int row = chunk >> 4;
            int d8 = (chunk & 15) * 8;
            uint32_t doff = (uint32_t)(row * ASTR + d8) * 2;
            size_t soff = koff + (size_t)row * HD + d8;
            CP_ASYNC16(base + doff,                     Kg_hi0 + soff);
            CP_ASYNC16(base + (64u*ASTR)*2 + doff,      Kg_lo0 + soff);
            CP_ASYNC16(base + (128u*ASTR)*2 + doff,     Vg_hi0 + soff);
            CP_ASYNC16(base + (192u*ASTR)*2 + doff,     Vg_lo0 + soff);
        }
        CP_COMMIT();
    };

    issue_kv(0, 0);

    for (int kb = 0; kb <= kbmax; kb++) {
        const int buf = kb & 1;
        CP_WAIT_ALL();
        __syncthreads();        // K/V(kb) visible; all warps done with other buf
        if (kb + 1 <= kbmax) issue_kv(buf ^ 1, kb + 1);

        const uint32_t kvb = smb + (uint32_t)(SM_KV + buf * KV_BUF) * 2;
        const uint32_t khB = kvb + kB_off;
        const uint32_t klB = kvb + (64u * ASTR) * 2 + kB_off;
        const uint32_t vhB = kvb + (128u * ASTR) * 2 + vB_off;
        const uint32_t vlB = kvb + (192u * ASTR) * 2 + vB_off;

        // ---- S = Q @ K^T ----
        float sacc[8][4];
        #pragma unroll
        for (int nt = 0; nt < 8; nt++)
            #pragma unroll
            for (int e = 0; e < 4; e++) sacc[nt][e] = 0.f;

        #pragma unroll
        for (int ks = 0; ks < 8; ks++) {
            const uint32_t k0b = (uint32_t)(ks * 32);   // ks*16 cols * 2B
            unsigned ah[4], al[4];
            LDSM_X4(ah[0], ah[1], ah[2], ah[3], qhiA + k0b);
            LDSM_X4(al[0], al[1], al[2], al[3], qloA + k0b);
            #pragma unroll
            for (int ntp = 0; ntp < 4; ntp++) {
                const uint32_t rowb = (uint32_t)(ntp * 16 * ASTR * 2);
                unsigned hk[4], lk[4];
                LDSM_X4(hk[0], hk[1], hk[2], hk[3], khB + rowb + k0b);
                LDSM_X4(lk[0], lk[1], lk[2], lk[3], klB + rowb + k0b);
                mma_bf16(sacc[2*ntp],   ah, hk[0], hk[1]);
                mma_bf16(sacc[2*ntp],   al, hk[0], hk[1]);
                mma_bf16(sacc[2*ntp],   ah, lk[0], lk[1]);
                mma_bf16(sacc[2*ntp+1], ah, hk[2], hk[3]);
                mma_bf16(sacc[2*ntp+1], al, hk[2], hk[3]);
                mma_bf16(sacc[2*ntp+1], ah, lk[2], lk[3]);
            }
        }

        // ---- scale + causal mask + online softmax ----
        float smax0 = -1e30f, smax1 = -1e30f;
        #pragma unroll
        for (int nt = 0; nt < 8; nt++) {
            int col = kb * 64 + nt * 8 + 2 * c;
            float v00 = sacc[nt][0] * SCALE; if (col     > r0) v00 = -1e30f;
            float v01 = sacc[nt][1] * SCALE; if (col + 1 > r0) v01 = -1e30f;
            float v10 = sacc[nt][2] * SCALE; if (col     > r1) v10 = -1e30f;
            float v11 = sacc[nt][3] * SCALE; if (col + 1 > r1) v11 = -1e30f;
            sacc[nt][0] = v00; sacc[nt][1] = v01;
            sacc[nt][2] = v10; sacc[nt][3] = v11;
            smax0 = fmaxf(smax0, fmaxf(v00, v01));
            smax1 = fmaxf(smax1, fmaxf(v10, v11));
        }
        smax0 = fmaxf(smax0, __shfl_xor_sync(0xffffffffu, smax0, 1));
        smax0 = fmaxf(smax0, __shfl_xor_sync(0xffffffffu, smax0, 2));
        smax1 = fmaxf(smax1, __shfl_xor_sync(0xffffffffu, smax1, 1));
        smax1 = fmaxf(smax1, __shfl_xor_sync(0xffffffffu, smax1, 2));

        float mnew0 = fmaxf(mrow[0], smax0);
        float mnew1 = fmaxf(mrow[1], smax1);
        float corr0 = __expf(mrow[0] - mnew0);
        float corr1 = __expf(mrow[1] - mnew1);
        mrow[0] = mnew0; mrow[1] = mnew1;

        float rsum0 = 0.f, rsum1 = 0.f;
        #pragma unroll
        for (int nt = 0; nt < 8; nt++) {
            float p00 = __expf(sacc[nt][0] - mnew0);
            float p01 = __expf(sacc[nt][1] - mnew0);
            float p10 = __expf(sacc[nt][2] - mnew1);
            float p11 = __expf(sacc[nt][3] - mnew1);
            rsum0 += p00 + p01;
            rsum1 += p10 + p11;
            sacc[nt][0] = p00; sacc[nt][1] = p01;
            sacc[nt][2] = p10; sacc[nt][3] = p11;
        }
        rsum0 += __shfl_xor_sync(0xffffffffu, rsum0, 1);
        rsum0 += __shfl_xor_sync(0xffffffffu, rsum0, 2);
        rsum1 += __shfl_xor_sync(0xffffffffu, rsum1, 1);
        rsum1 += __shfl_xor_sync(0xffffffffu, rsum1, 2);
        lrow2[0] = lrow2[0] * corr0 + rsum0;
        lrow2[1] = lrow2[1] * corr1 + rsum1;

        #pragma unroll
        for (int nt = 0; nt < 16; nt++) {
            o[nt][0] *= corr0; o[nt][1] *= corr0;
            o[nt][2] *= corr1; o[nt][3] *= corr1;
        }

        // ---- O += P @ V  (P fragments directly from sacc registers) ----
        #pragma unroll
        for (int ks = 0; ks < 4; ks++) {
            unsigned pah[4], pal[4];
            split2(sacc[2*ks][0],   sacc[2*ks][1],   pah[0], pal[0]);
            split2(sacc[2*ks][2],   sacc[2*ks][3],   pah[1], pal[1]);
            split2(sacc[2*ks+1][0], sacc[2*ks+1][1], pah[2], pal[2]);
            split2(sacc[2*ks+1][2], sacc[2*ks+1][3], pah[3], pal[3]);
            const uint32_t srowb = (uint32_t)(ks * 16 * ASTR * 2);
            #pragma unroll
            for (int ntp = 0; ntp < 8; ntp++) {
                const uint32_t dcolb = (uint32_t)(ntp * 16 * 2);
                unsigned hv[4], lv[4];
                LDSM_X4_T(hv[0], hv[1], hv[2], hv[3], vhB + srowb + dcolb);
                LDSM_X4_T(lv[0], lv[1], lv[2], lv[3], vlB + srowb + dcolb);
                mma_bf16(o[2*ntp],   pah, hv[0], hv[1]);
                mma_bf16(o[2*ntp],   pal, hv[0], hv[1]);
                mma_bf16(o[2*ntp],   pah, lv[0], lv[1]);
                mma_bf16(o[2*ntp+1], pah, hv[2], hv[3]);
                mma_bf16(o[2*ntp+1], pal, hv[2], hv[3]);
                mma_bf16(o[2*ntp+1], pah, lv[2], lv[3]);
            }
        }
    }

    // ---- normalize + write ctx ----
    float inv0 = 1.0f / lrow2[0];
    float inv1 = 1.0f / lrow2[1];
    int s0 = qb * 128 + m0 + g;
    size_t base0 = ((size_t)b * SEQ + s0) * DM + h * HD;
    size_t base1 = ((size_t)b * SEQ + s0 + 8) * DM + h * HD;
    #pragma unroll
    for (int nt = 0; nt < 16; nt++) {
        int d0 = nt * 8 + 2 * c;
        float2 w0 = {o[nt][0] * inv0, o[nt][1] * inv0};
        float2 w1 = {o[nt][2] * inv1, o[nt][3] * inv1};
        *(float2*)(g_ctx + base0 + d0) = w0;
        *(float2*)(g_ctx + base1 + d0) = w1;
    }
}

// ---------------- launch ----------------------------------------------------
extern "C" void kernel_launch(void* const* d_in, const int* in_sizes, int n_in,
                              void* d_out, int out_size) {
    const float* x      = (const float*)d_in[0];
    // d_in[1] = attn_mask (causal, recomputed on the fly; unused)
    const float* Wqkv_w = (const float*)d_in[2];
    const float* Wqkv_b = (const float*)d_in[3];
    const float* out_w  = (const float*)d_in[4];
    const float* out_b  = (const float*)d_in[5];
    float* out = (float*)d_out;

    build_rope_kernel<<<(SEQ * 64 + 255) / 256, 256>>>();

    cudaFuncSetAttribute(qkv_gemm_kernel,
                         cudaFuncAttributeMaxDynamicSharedMemorySize, GEMM_SMEM_BYTES);
    cudaFuncSetAttribute(out_gemm_kernel,
                         cudaFuncAttributeMaxDynamicSharedMemorySize, GEMM_SMEM_BYTES);

    qkv_gemm_kernel<<<dim3(NQKV / 128, MROWS / 128), GEMM_NTHREADS,
                      GEMM_SMEM_BYTES>>>(x, Wqkv_w, Wqkv_b);

    cudaFuncSetAttribute(attn_mma_kernel,
                         cudaFuncAttributeMaxDynamicSharedMemorySize, ATTN_SMEM_BYTES);
    attn_mma_kernel<<<dim3(SEQ / 128, BATCH * NH), 256, ATTN_SMEM_BYTES>>>();

    out_gemm_kernel<<<dim3(DM / 128, MROWS / 128), GEMM_NTHREADS,
                      GEMM_SMEM_BYTES>>>(out_w, out_b, out);
}

// round 15
// speedup vs baseline: 1.9372x; 1.2260x over previous
#include <cuda_runtime.h>
#include <cuda_bf16.h>
#include <cuda_fp16.h>
#include <cstdint>
#include <stdint.h>
#include <math.h>

#define BATCH 2
#define SEQ 2048
#define NH 16
#define HD 128
#define DM 2048
#define MROWS (BATCH*SEQ)     // 4096
#define NQKV (3*DM)           // 6144
#define SCALE 0.08838834764831845f  // 1/sqrt(128)

// ---------------- scratch (static device globals: allocation-free) ----------
__device__ unsigned short g_Qhi[BATCH*NH*SEQ*HD];
__device__ unsigned short g_Qlo[BATCH*NH*SEQ*HD];
__device__ unsigned short g_Khi[BATCH*NH*SEQ*HD];
__device__ unsigned short g_Klo[BATCH*NH*SEQ*HD];
__device__ unsigned short g_Vhi[BATCH*NH*SEQ*HD];
__device__ unsigned short g_Vlo[BATCH*NH*SEQ*HD];
__device__ __half g_ctxh[MROWS*DM];      // ctx, fp16 (written by attention)
__device__ __half g_Xh[MROWS*DM];        // fp16 copies of GEMM operands
__device__ __half g_Wqkvh[NQKV*DM];
__device__ __half g_OWh[DM*DM];
__device__ float g_cos[SEQ*64];
__device__ float g_sin[SEQ*64];

// ---------------- RoPE table -------------------------------------------------
__global__ void build_rope_kernel() {
    int idx = blockIdx.x * blockDim.x + threadIdx.x;
    if (idx >= SEQ * 64) return;
    int pos = idx >> 6, i = idx & 63;
    double f = pow(10000.0, -(double)i / 64.0);
    double a = (double)pos * f;
    g_cos[idx] = (float)cos(a);
    g_sin[idx] = (float)sin(a);
}

// ---------------- fp32 -> fp16 pre-convert (grid-stride, float4) -------------
__global__ void cvt_h_kernel(const float* __restrict__ src,
                             __half* __restrict__ dst, int n4) {
    int i = blockIdx.x * blockDim.x + threadIdx.x;
    int stride = gridDim.x * blockDim.x;
    for (; i < n4; i += stride) {
        float4 v = *(const float4*)(src + (size_t)i * 4);
        __half2 h0 = __floats2half2_rn(v.x, v.y);
        __half2 h1 = __floats2half2_rn(v.z, v.w);
        *(__half2*)(dst + (size_t)i * 4)     = h0;
        *(__half2*)(dst + (size_t)i * 4 + 2) = h1;
    }
}

// ---------------- mma / ldmatrix / cp.async helpers --------------------------
__device__ __forceinline__ void mma_f16_r(float (&cacc)[4],
                                          const unsigned (&a)[4],
                                          unsigned b0, unsigned b1) {
    asm volatile(
        "mma.sync.aligned.m16n8k16.row.col.f32.f16.f16.f32 "
        "{%0,%1,%2,%3}, {%4,%5,%6,%7}, {%8,%9}, {%0,%1,%2,%3};\n"
        : "+f"(cacc[0]), "+f"(cacc[1]), "+f"(cacc[2]), "+f"(cacc[3])
        : "r"(a[0]), "r"(a[1]), "r"(a[2]), "r"(a[3]), "r"(b0), "r"(b1));
}

__device__ __forceinline__ void mma_bf16(float (&cacc)[4],
                                         const unsigned int (&a)[4],
                                         unsigned int b0, unsigned int b1) {
    asm volatile(
        "mma.sync.aligned.m16n8k16.row.col.f32.bf16.bf16.f32 "
        "{%0,%1,%2,%3}, {%4,%5,%6,%7}, {%8,%9}, {%0,%1,%2,%3};\n"
        : "+f"(cacc[0]), "+f"(cacc[1]), "+f"(cacc[2]), "+f"(cacc[3])
        : "r"(a[0]), "r"(a[1]), "r"(a[2]), "r"(a[3]), "r"(b0), "r"(b1));
}

// split two floats into packed bf16 hi pair + bf16 residual-lo pair
__device__ __forceinline__ void split2(float a, float b,
                                       unsigned int &hi, unsigned int &lo) {
    __nv_bfloat16 ha = __float2bfloat16(a);
    __nv_bfloat16 hb = __float2bfloat16(b);
    float ra = a - __bfloat162float(ha);
    float rb = b - __bfloat162float(hb);
    __nv_bfloat16 la = __float2bfloat16(ra);
    __nv_bfloat16 lb = __float2bfloat16(rb);
    hi = (unsigned int)__bfloat16_as_ushort(ha) |
         ((unsigned int)__bfloat16_as_ushort(hb) << 16);
    lo = (unsigned int)__bfloat16_as_ushort(la) |
         ((unsigned int)__bfloat16_as_ushort(lb) << 16);
}

#define LDSM_X4(r0, r1, r2, r3, addr) \
    asm volatile("ldmatrix.sync.aligned.m8n8.x4.shared.b16 {%0,%1,%2,%3}, [%4];" \
        : "=r"(r0), "=r"(r1), "=r"(r2), "=r"(r3) : "r"(addr))

#define LDSM_X4_T(r0, r1, r2, r3, addr) \
    asm volatile("ldmatrix.sync.aligned.m8n8.x4.trans.shared.b16 {%0,%1,%2,%3}, [%4];" \
        : "=r"(r0), "=r"(r1), "=r"(r2), "=r"(r3) : "r"(addr))

#define CP_ASYNC16(dst_u32, src_ptr) \
    asm volatile("cp.async.cg.shared.global [%0], [%1], 16;" \
        :: "r"(dst_u32), "l"(src_ptr) : "memory")

#define CP_COMMIT() asm volatile("cp.async.commit_group;" ::: "memory")
#define CP_WAIT_ALL() asm volatile("cp.async.wait_group 0;" ::: "memory")
#define CP_WAIT_1() asm volatile("cp.async.wait_group 1;" ::: "memory")

__device__ __forceinline__ uint32_t smem_u32_of(const void* p) {
    uint32_t a;
    asm("{ .reg .u64 t; cvta.to.shared.u64 t, %1; cvt.u32.u64 %0, t; }"
        : "=r"(a) : "l"(p));
    return a;
}

// ---------------- fp16 GEMM: cp.async 3-stage + ldmatrix ---------------------
// 128x128 tile, BK=32, 256 threads = 8 warps (2m x 4n), warp tile 64x32.
// smem: per stage A[128][40] + B[128][40] halfs (stride 40 -> ldmatrix
// bank-free: row banks 20r mod 32 tile all 32 banks per 8-row footprint).
// Warp n-cols: nt0,1 = nwarp*16+{0,8}; nt2,3 = 64+nwarp*16+{0,8}
// -> (acc[nt], acc[nt+2]) is the RoPE pair (d, d+64).
#define GEMM_NTHREADS 256
#define GSTR 40
#define STAGE_BYTES (2*128*GSTR*2)            // 20480
#define GEMM_SMEM_BYTES (3*STAGE_BYTES)       // 61440

__device__ __forceinline__ void gemm_f16_mainloop(
    const __half* __restrict__ Ag, const __half* __restrict__ Bg,
    int K, uint32_t smb, float (&acc)[4][4][4])
{
    const int tid = threadIdx.x;
    const int lane = tid & 31;
    const int wid = tid >> 5;
    const int mwarp = wid >> 2;
    const int nwarp = wid & 3;
    const int KT = K >> 5;

    // cp.async per-thread: 2 chunks A + 2 chunks B per tile
    const int crow0 = tid >> 2;                    // 0..63
    const int crow1 = crow0 + 64;
    const int cc8 = (tid & 3) * 8;
    const uint32_t cdst0 = (uint32_t)(crow0 * GSTR + cc8) * 2;
    const uint32_t cdst1 = (uint32_t)(crow1 * GSTR + cc8) * 2;

    // ldmatrix lane-constant offsets (bytes)
    const int lrow = lane & 7;
    const int lj = lane >> 3;
    const uint32_t aOffBase = (uint32_t)(((mwarp * 64 + lrow + (lj & 1) * 8) * GSTR +
                                          (lj >> 1) * 8) * 2);
    const uint32_t bOffBase = (uint32_t)(((nwarp * 16 + lrow + (lj >> 1) * 8) * GSTR +
                                          (lj & 1) * 8) * 2);

    auto issue = [&](int t) {
        const uint32_t sb = smb + (uint32_t)(t % 3) * STAGE_BYTES;
        const __half* As = Ag + (size_t)t * 32;
        const __half* Bs = Bg + (size_t)t * 32;
        CP_ASYNC16(sb + cdst0, As + (size_t)crow0 * K + cc8);
        CP_ASYNC16(sb + cdst1, As + (size_t)crow1 * K + cc8);
        CP_ASYNC16(sb + STAGE_BYTES/2 + cdst0, Bs + (size_t)crow0 * K + cc8);
        CP_ASYNC16(sb + STAGE_BYTES/2 + cdst1, Bs + (size_t)crow1 * K + cc8);
        CP_COMMIT();
    };

    issue(0);
    if (KT > 1) issue(1);

    for (int t = 0; t < KT; t++) {
        CP_WAIT_1();
        __syncthreads();
        if (t + 2 < KT) issue(t + 2);

        const uint32_t sb = smb + (uint32_t)(t % 3) * STAGE_BYTES;
        const uint32_t aB = sb + aOffBase;
        const uint32_t bB = sb + STAGE_BYTES/2 + bOffBase;

        #pragma unroll
        for (int ks = 0; ks < 2; ks++) {
            const uint32_t kofs = (uint32_t)(ks * 32);   // 16 halfs
            unsigned a4[4][4];
            #pragma unroll
            for (int mt = 0; mt < 4; mt++)
                LDSM_X4(a4[mt][0], a4[mt][1], a4[mt][2], a4[mt][3],
                        aB + (uint32_t)(mt * 16 * GSTR * 2) + kofs);
            #pragma unroll
            for (int grp = 0; grp < 2; grp++) {
                unsigned b0, b1, b2, b3;
                LDSM_X4(b0, b1, b2, b3,
                        bB + (uint32_t)(grp * 64 * GSTR * 2) + kofs);
                #pragma unroll
                for (int mt = 0; mt < 4; mt++) {
                    mma_f16_r(acc[mt][grp * 2],     a4[mt], b0, b1);
                    mma_f16_r(acc[mt][grp * 2 + 1], a4[mt], b2, b3);
                }
            }
        }
        __syncthreads();   // all warps done with stage t before it is refilled
    }
}

// ---------------- QKV GEMM with fused bias + RoPE + bf16-split scatter ------
__global__ void __launch_bounds__(GEMM_NTHREADS, 2) qkv_gemm_kernel(
    const float* __restrict__ bias)
{
    extern __shared__ __align__(16) char smem[];
    const uint32_t smb = smem_u32_of(smem);
    float acc[4][4][4];
    #pragma unroll
    for (int i = 0; i < 4; i++)
        #pragma unroll
        for (int j = 0; j < 4; j++)
            #pragma unroll
            for (int k = 0; k < 4; k++) acc[i][j][k] = 0.f;

    const int m0 = blockIdx.y * 128;
    const int n0 = blockIdx.x * 128;
    gemm_f16_mainloop(g_Xh + (size_t)m0 * DM, g_Wqkvh + (size_t)n0 * DM,
                      DM, smb, acc);

    const int tid = threadIdx.x;
    const int lane = tid & 31;
    const int wid = tid >> 5;
    const int g = lane >> 2, c = lane & 3;
    const int mwarp = wid >> 2, nwarp = wid & 3;

    const int comp = n0 >> 11;            // 0=Q, 1=K, 2=V
    const int h = (n0 >> 7) & 15;
    unsigned short* dhi = (comp == 0) ? g_Qhi : (comp == 1) ? g_Khi : g_Vhi;
    unsigned short* dlo = (comp == 0) ? g_Qlo : (comp == 1) ? g_Klo : g_Vlo;

    #pragma unroll
    for (int mt = 0; mt < 4; mt++) {
        #pragma unroll
        for (int rr = 0; rr < 2; rr++) {
            int m = m0 + mwarp * 64 + mt * 16 + g + rr * 8;
            int bb = m >> 11, s = m & 2047;
            size_t base = ((size_t)(bb * NH + h) * SEQ + s) * HD;
            #pragma unroll
            for (int ntp = 0; ntp < 2; ntp++) {
                int d0 = nwarp * 16 + ntp * 8 + 2 * c;       // 0..63
                float v0e0 = acc[mt][ntp][rr * 2]     + bias[n0 + d0];
                float v0e1 = acc[mt][ntp][rr * 2 + 1] + bias[n0 + d0 + 1];
                float v1e0 = acc[mt][ntp + 2][rr * 2]     + bias[n0 + 64 + d0];
                float v1e1 = acc[mt][ntp + 2][rr * 2 + 1] + bias[n0 + 64 + d0 + 1];
                unsigned int hi, lo;
                if (comp == 2) {
                    split2(v0e0, v0e1, hi, lo);
                    *(unsigned int*)&dhi[base + d0] = hi;
                    *(unsigned int*)&dlo[base + d0] = lo;
                    split2(v1e0, v1e1, hi, lo);
                    *(unsigned int*)&dhi[base + 64 + d0] = hi;
                    *(unsigned int*)&dlo[base + 64 + d0] = lo;
                } else {
                    float2 cs = *(const float2*)&g_cos[s * 64 + d0];
                    float2 sn = *(const float2*)&g_sin[s * 64 + d0];
                    float q0e0 = v0e0 * cs.x - v1e0 * sn.x;
                    float q0e1 = v0e1 * cs.y - v1e1 * sn.y;
                    float q1e0 = v1e0 * cs.x + v0e0 * sn.x;
                    float q1e1 = v1e1 * cs.y + v0e1 * sn.y;
                    split2(q0e0, q0e1, hi, lo);
                    *(unsigned int*)&dhi[base + d0] = hi;
                    *(unsigned int*)&dlo[base + d0] = lo;
                    split2(q1e0, q1e1, hi, lo);
                    *(unsigned int*)&dhi[base + 64 + d0] = hi;
                    *(unsigned int*)&dlo[base + 64 + d0] = lo;
                }
            }
        }
    }
}

// ---------------- output projection GEMM (reads g_ctxh) ---------------------
__global__ void __launch_bounds__(GEMM_NTHREADS, 2) out_gemm_kernel(
    const float* __restrict__ bias, float* __restrict__ C)
{
    extern __shared__ __align__(16) char smem[];
    const uint32_t smb = smem_u32_of(smem);
    float acc[4][4][4];
    #pragma unroll
    for (int i = 0; i < 4; i++)
        #pragma unroll
        for (int j = 0; j < 4; j++)
            #pragma unroll
            for (int k = 0; k < 4; k++) acc[i][j][k] = 0.f;

    const int m0 = blockIdx.y * 128;
    const int n0 = blockIdx.x * 128;
    gemm_f16_mainloop(g_ctxh + (size_t)m0 * DM, g_OWh + (size_t)n0 * DM,
                      DM, smb, acc);

    const int tid = threadIdx.x;
    const int lane = tid & 31;
    const int wid = tid >> 5;
    const int g = lane >> 2, c = lane & 3;
    const int mwarp = wid >> 2, nwarp = wid & 3;

    #pragma unroll
    for (int mt = 0; mt < 4; mt++) {
        #pragma unroll
        for (int rr = 0; rr < 2; rr++) {
            int row = m0 + mwarp * 64 + mt * 16 + g + rr * 8;
            #pragma unroll
            for (int nt = 0; nt < 4; nt++) {
                int colb = n0 + nwarp * 16 + (nt & 1) * 8 + (nt >> 1) * 64 + 2 * c;
                float2 st;
                st.x = acc[mt][nt][rr * 2]     + bias[colb];
                st.y = acc[mt][nt][rr * 2 + 1] + bias[colb + 1];
                *(float2*)(C + (size_t)row * DM + colb) = st;
            }
        }
    }
}

// ---------------- flash attention: ldmatrix + cp.async + register-P ---------
#define ASTR 136
#define SM_QHI 0
#define SM_QLO (128*ASTR)              // 17408 ushorts
#define SM_KV  (2*128*ASTR)            // 34816
#define KV_BUF (4*64*ASTR)             // 34816 ushorts per buffer
#define ATTN_SMEM_BYTES ((SM_KV + 2*KV_BUF) * 2)   // 208896

__global__ void __launch_bounds__(256) attn_mma_kernel() {
    extern __shared__ __align__(16) unsigned short sm[];
    const uint32_t smb = smem_u32_of(sm);

    const int tid = threadIdx.x;
    const int lane = tid & 31;
    const int wid = tid >> 5;
    const int g = lane >> 2;           // 0..7
    const int c = lane & 3;            // 0..3
    const int m0 = wid * 16;
    const int qb = blockIdx.x;         // 0..15
    const int bh = blockIdx.y;         // 0..31
    const int b = bh >> 4, h = bh & 15;

    const size_t bhoff = (size_t)bh * SEQ * HD;
    const unsigned short* Qg_hi = g_Qhi + bhoff + (size_t)qb * 128 * HD;
    const unsigned short* Qg_lo = g_Qlo + bhoff + (size_t)qb * 128 * HD;
    const unsigned short* Kg_hi0 = g_Khi + bhoff;
    const unsigned short* Kg_lo0 = g_Klo + bhoff;
    const unsigned short* Vg_hi0 = g_Vhi + bhoff;
    const unsigned short* Vg_lo0 = g_Vlo + bhoff;

    // ---- load Q (128x128 hi+lo, straight copy) ----
    #pragma unroll
    for (int it = 0; it < 16; it++) {
        int idx = tid + it * 256;                 // 0..4095
        const unsigned short* src = (it < 8) ? Qg_hi : Qg_lo;
        unsigned short* dst = (it < 8) ? (sm + SM_QHI) : (sm + SM_QLO);
        int rem = idx & 2047;
        int row = rem >> 4, d = (rem & 15) * 8;
        *(uint4*)&dst[row * ASTR + d] = *(const uint4*)&src[row * HD + d];
    }

    const int lrow = lane & 7;
    const int lj = lane >> 3;
    const uint32_t qA_off = (uint32_t)(((m0 + lrow + (lj & 1) * 8) * ASTR +
                                        (lj >> 1) * 8) * 2);
    const uint32_t qhiA = smb + SM_QHI * 2 + qA_off;
    const uint32_t qloA = smb + SM_QLO * 2 + qA_off;
    const uint32_t kB_off = (uint32_t)(((lrow + (lj >> 1) * 8) * ASTR +
                                        (lj & 1) * 8) * 2);
    const uint32_t vB_off = (uint32_t)(((lrow + (lj & 1) * 8) * ASTR +
                                        (lj >> 1) * 8) * 2);

    float o[16][4];
    float mrow[2], lrow2[2];
    #pragma unroll
    for (int i = 0; i < 16; i++)
        #pragma unroll
        for (int j = 0; j < 4; j++) o[i][j] = 0.f;
    mrow[0] = mrow[1] = -1e30f;
    lrow2[0] = lrow2[1] = 0.f;

    const int r0 = qb * 128 + m0 + g;
    const int r1 = r0 + 8;
    const int kbmax = 2 * qb + 1;

    auto issue_kv = [&](int buf, int kb) {
        const size_t koff = (size_t)kb * 64 * HD;
        const uint32_t base = smb + (uint32_t)(SM_KV + buf * KV_BUF) * 2;
        #pragma unroll
        for (int it = 0; it < 4; it++) {
            int chunk = tid + it * 256;           // 0..1023
            int row = chunk >> 4;
            int d8 = (chunk & 15) * 8;
            uint32_t doff = (uint32_t)(row * ASTR + d8) * 2;
            size_t soff = koff + (size_t)row * HD + d8;
            CP_ASYNC16(base + doff,                     Kg_hi0 + soff);
            CP_ASYNC16(base + (64u*ASTR)*2 + doff,      Kg_lo0 + soff);
            CP_ASYNC16(base + (128u*ASTR)*2 + doff,     Vg_hi0 + soff);
            CP_ASYNC16(base + (192u*ASTR)*2 + doff,     Vg_lo0 + soff);
        }
        CP_COMMIT();
    };

    issue_kv(0, 0);

    for (int kb = 0; kb <= kbmax; kb++) {
        const int buf = kb & 1;
        CP_WAIT_ALL();
        __syncthreads();
        if (kb + 1 <= kbmax) issue_kv(buf ^ 1, kb + 1);

        const uint32_t kvb = smb + (uint32_t)(SM_KV + buf * KV_BUF) * 2;
        const uint32_t khB = kvb + kB_off;
        const uint32_t klB = kvb + (64u * ASTR) * 2 + kB_off;
        const uint32_t vhB = kvb + (128u * ASTR) * 2 + vB_off;
        const uint32_t vlB = kvb + (192u * ASTR) * 2 + vB_off;

        // ---- S = Q @ K^T ----
        float sacc[8][4];
        #pragma unroll
        for (int nt = 0; nt < 8; nt++)
            #pragma unroll
            for (int e = 0; e < 4; e++) sacc[nt][e] = 0.f;

        #pragma unroll
        for (int ks = 0; ks < 8; ks++) {
            const uint32_t k0b = (uint32_t)(ks * 32);
            unsigned ah[4], al[4];
            LDSM_X4(ah[0], ah[1], ah[2], ah[3], qhiA + k0b);
            LDSM_X4(al[0], al[1], al[2], al[3], qloA + k0b);
            #pragma unroll
            for (int ntp = 0; ntp < 4; ntp++) {
                const uint32_t rowb = (uint32_t)(ntp * 16 * ASTR * 2);
                unsigned hk[4], lk[4];
                LDSM_X4(hk[0], hk[1], hk[2], hk[3], khB + rowb + k0b);
                LDSM_X4(lk[0], lk[1], lk[2], lk[3], klB + rowb + k0b);
                mma_bf16(sacc[2*ntp],   ah, hk[0], hk[1]);
                mma_bf16(sacc[2*ntp],   al, hk[0], hk[1]);
                mma_bf16(sacc[2*ntp],   ah, lk[0], lk[1]);
                mma_bf16(sacc[2*ntp+1], ah, hk[2], hk[3]);
                mma_bf16(sacc[2*ntp+1], al, hk[2], hk[3]);
                mma_bf16(sacc[2*ntp+1], ah, lk[2], lk[3]);
            }
        }

        // ---- scale + causal mask + online softmax ----
        float smax0 = -1e30f, smax1 = -1e30f;
        #pragma unroll
        for (int nt = 0; nt < 8; nt++) {
            int col = kb * 64 + nt * 8 + 2 * c;
            float v00 = sacc[nt][0] * SCALE; if (col     > r0) v00 = -1e30f;
            float v01 = sacc[nt][1] * SCALE; if (col + 1 > r0) v01 = -1e30f;
            float v10 = sacc[nt][2] * SCALE; if (col     > r1) v10 = -1e30f;
            float v11 = sacc[nt][3] * SCALE; if (col + 1 > r1) v11 = -1e30f;
            sacc[nt][0] = v00; sacc[nt][1] = v01;
            sacc[nt][2] = v10; sacc[nt][3] = v11;
            smax0 = fmaxf(smax0, fmaxf(v00, v01));
            smax1 = fmaxf(smax1, fmaxf(v10, v11));
        }
        smax0 = fmaxf(smax0, __shfl_xor_sync(0xffffffffu, smax0, 1));
        smax0 = fmaxf(smax0, __shfl_xor_sync(0xffffffffu, smax0, 2));
        smax1 = fmaxf(smax1, __shfl_xor_sync(0xffffffffu, smax1, 1));
        smax1 = fmaxf(smax1, __shfl_xor_sync(0xffffffffu, smax1, 2));

        float mnew0 = fmaxf(mrow[0], smax0);
        float mnew1 = fmaxf(mrow[1], smax1);
        float corr0 = __expf(mrow[0] - mnew0);
        float corr1 = __expf(mrow[1] - mnew1);
        mrow[0] = mnew0; mrow[1] = mnew1;

        float rsum0 = 0.f, rsum1 = 0.f;
        #pragma unroll
        for (int nt = 0; nt < 8; nt++) {
            float p00 = __expf(sacc[nt][0] - mnew0);
            float p01 = __expf(sacc[nt][1] - mnew0);
            float p10 = __expf(sacc[nt][2] - mnew1);
            float p11 = __expf(sacc[nt][3] - mnew1);
            rsum0 += p00 + p01;
            rsum1 += p10 + p11;
            sacc[nt][0] = p00; sacc[nt][1] = p01;
            sacc[nt][2] = p10; sacc[nt][3] = p11;
        }
        rsum0 += __shfl_xor_sync(0xffffffffu, rsum0, 1);
        rsum0 += __shfl_xor_sync(0xffffffffu, rsum0, 2);
        rsum1 += __shfl_xor_sync(0xffffffffu, rsum1, 1);
        rsum1 += __shfl_xor_sync(0xffffffffu, rsum1, 2);
        lrow2[0] = lrow2[0] * corr0 + rsum0;
        lrow2[1] = lrow2[1] * corr1 + rsum1;

        #pragma unroll
        for (int nt = 0; nt < 16; nt++) {
            o[nt][0] *= corr0; o[nt][1] *= corr0;
            o[nt][2] *= corr1; o[nt][3] *= corr1;
        }

        // ---- O += P @ V  (P fragments directly from sacc registers) ----
        #pragma unroll
        for (int ks = 0; ks < 4; ks++) {
            unsigned pah[4], pal[4];
            split2(sacc[2*ks][0],   sacc[2*ks][1],   pah[0], pal[0]);
            split2(sacc[2*ks][2],   sacc[2*ks][3],   pah[1], pal[1]);
            split2(sacc[2*ks+1][0], sacc[2*ks+1][1], pah[2], pal[2]);
            split2(sacc[2*ks+1][2], sacc[2*ks+1][3], pah[3], pal[3]);
            const uint32_t srowb = (uint32_t)(ks * 16 * ASTR * 2);
            #pragma unroll
            for (int ntp = 0; ntp < 8; ntp++) {
                const uint32_t dcolb = (uint32_t)(ntp * 16 * 2);
                unsigned hv[4], lv[4];
                LDSM_X4_T(hv[0], hv[1], hv[2], hv[3], vhB + srowb + dcolb);
                LDSM_X4_T(lv[0], lv[1], lv[2], lv[3], vlB + srowb + dcolb);
                mma_bf16(o[2*ntp],   pah, hv[0], hv[1]);
                mma_bf16(o[2*ntp],   pal, hv[0], hv[1]);
                mma_bf16(o[2*ntp],   pah, lv[0], lv[1]);
                mma_bf16(o[2*ntp+1], pah, hv[2], hv[3]);
                mma_bf16(o[2*ntp+1], pal, hv[2], hv[3]);
                mma_bf16(o[2*ntp+1], pah, lv[2], lv[3]);
            }
        }
    }

    // ---- normalize + write ctx as fp16 (same rounding as old in-GEMM cvt) --
    float inv0 = 1.0f / lrow2[0];
    float inv1 = 1.0f / lrow2[1];
    int s0 = qb * 128 + m0 + g;
    size_t base0 = ((size_t)b * SEQ + s0) * DM + h * HD;
    size_t base1 = ((size_t)b * SEQ + s0 + 8) * DM + h * HD;
    #pragma unroll
    for (int nt = 0; nt < 16; nt++) {
        int d0 = nt * 8 + 2 * c;
        *(__half2*)&g_ctxh[base0 + d0] =
            __floats2half2_rn(o[nt][0] * inv0, o[nt][1] * inv0);
        *(__half2*)&g_ctxh[base1 + d0] =
            __floats2half2_rn(o[nt][2] * inv1, o[nt][3] * inv1);
    }
}

// ---------------- launch ----------------------------------------------------
extern "C" void kernel_launch(void* const* d_in, const int* in_sizes, int n_in,
                              void* d_out, int out_size) {
    const float* x      = (const float*)d_in[0];
    // d_in[1] = attn_mask (causal, recomputed on the fly; unused)
    const float* Wqkv_w = (const float*)d_in[2];
    const float* Wqkv_b = (const float*)d_in[3];
    const float* out_w  = (const float*)d_in[4];
    const float* out_b  = (const float*)d_in[5];
    float* out = (float*)d_out;

    build_rope_kernel<<<(SEQ * 64 + 255) / 256, 256>>>();

    // fp16 pre-conversion of GEMM operands (rn, same rounding as before)
    __half* xh;  cudaGetSymbolAddress((void**)&xh,  g_Xh);
    __half* wh;  cudaGetSymbolAddress((void**)&wh,  g_Wqkvh);
    __half* owh; cudaGetSymbolAddress((void**)&owh, g_OWh);
    cvt_h_kernel<<<592, 256>>>(x, xh, MROWS * DM / 4);
    cvt_h_kernel<<<592, 256>>>(Wqkv_w, wh, NQKV * DM / 4);
    cvt_h_kernel<<<592, 256>>>(out_w, owh, DM * DM / 4);

    cudaFuncSetAttribute(qkv_gemm_kernel,
                         cudaFuncAttributeMaxDynamicSharedMemorySize, GEMM_SMEM_BYTES);
    cudaFuncSetAttribute(out_gemm_kernel,
                         cudaFuncAttributeMaxDynamicSharedMemorySize, GEMM_SMEM_BYTES);

    qkv_gemm_kernel<<<dim3(NQKV / 128, MROWS / 128), GEMM_NTHREADS,
                      GEMM_SMEM_BYTES>>>(Wqkv_b);

    cudaFuncSetAttribute(attn_mma_kernel,
                         cudaFuncAttributeMaxDynamicSharedMemorySize, ATTN_SMEM_BYTES);
    attn_mma_kernel<<<dim3(SEQ / 128, BATCH * NH), 256, ATTN_SMEM_BYTES>>>();

    out_gemm_kernel<<<dim3(DM / 128, MROWS / 128), GEMM_NTHREADS,
                      GEMM_SMEM_BYTES>>>(out_b, out);
}

// round 16
// speedup vs baseline: 2.5948x; 1.3394x over previous
#include <cuda_runtime.h>
#include <cuda_bf16.h>
#include <cuda_fp16.h>
#include <cstdint>
#include <stdint.h>
#include <math.h>

#define BATCH 2
#define SEQ 2048
#define NH 16
#define HD 128
#define DM 2048
#define MROWS (BATCH*SEQ)     // 4096
#define NQKV (3*DM)           // 6144
#define SCALE 0.08838834764831845f  // 1/sqrt(128)

// ---------------- scratch (static device globals: allocation-free) ----------
__device__ __half g_Qh[BATCH*NH*SEQ*HD];   // fp16 Q/K/V [b,h,s,d]
__device__ __half g_Kh[BATCH*NH*SEQ*HD];
__device__ __half g_Vh[BATCH*NH*SEQ*HD];
__device__ __half g_ctxh[MROWS*DM];        // ctx, fp16 (written by attention)
__device__ __half g_Xh[MROWS*DM];          // fp16 copies of GEMM operands
__device__ __half g_Wqkvh[NQKV*DM];
__device__ __half g_OWh[DM*DM];
__device__ float g_cos[SEQ*64];
__device__ float g_sin[SEQ*64];

// ---------------- RoPE table -------------------------------------------------
__global__ void build_rope_kernel() {
    int idx = blockIdx.x * blockDim.x + threadIdx.x;
    if (idx >= SEQ * 64) return;
    int pos = idx >> 6, i = idx & 63;
    double f = pow(10000.0, -(double)i / 64.0);
    double a = (double)pos * f;
    g_cos[idx] = (float)cos(a);
    g_sin[idx] = (float)sin(a);
}

// ---------------- fp32 -> fp16 pre-convert (grid-stride, float4) -------------
__global__ void cvt_h_kernel(const float* __restrict__ src,
                             __half* __restrict__ dst, int n4) {
    int i = blockIdx.x * blockDim.x + threadIdx.x;
    int stride = gridDim.x * blockDim.x;
    for (; i < n4; i += stride) {
        float4 v = *(const float4*)(src + (size_t)i * 4);
        __half2 h0 = __floats2half2_rn(v.x, v.y);
        __half2 h1 = __floats2half2_rn(v.z, v.w);
        *(__half2*)(dst + (size_t)i * 4)     = h0;
        *(__half2*)(dst + (size_t)i * 4 + 2) = h1;
    }
}

// ---------------- mma / ldmatrix / cp.async helpers --------------------------
__device__ __forceinline__ void mma_f16_r(float (&cacc)[4],
                                          const unsigned (&a)[4],
                                          unsigned b0, unsigned b1) {
    asm volatile(
        "mma.sync.aligned.m16n8k16.row.col.f32.f16.f16.f32 "
        "{%0,%1,%2,%3}, {%4,%5,%6,%7}, {%8,%9}, {%0,%1,%2,%3};\n"
        : "+f"(cacc[0]), "+f"(cacc[1]), "+f"(cacc[2]), "+f"(cacc[3])
        : "r"(a[0]), "r"(a[1]), "r"(a[2]), "r"(a[3]), "r"(b0), "r"(b1));
}

__device__ __forceinline__ unsigned f2h2u(float lo, float hi) {
    __half2 h = __floats2half2_rn(lo, hi);
    return *(unsigned*)&h;
}

#define LDSM_X4(r0, r1, r2, r3, addr) \
    asm volatile("ldmatrix.sync.aligned.m8n8.x4.shared.b16 {%0,%1,%2,%3}, [%4];" \
        : "=r"(r0), "=r"(r1), "=r"(r2), "=r"(r3) : "r"(addr))

#define LDSM_X4_T(r0, r1, r2, r3, addr) \
    asm volatile("ldmatrix.sync.aligned.m8n8.x4.trans.shared.b16 {%0,%1,%2,%3}, [%4];" \
        : "=r"(r0), "=r"(r1), "=r"(r2), "=r"(r3) : "r"(addr))

#define CP_ASYNC16(dst_u32, src_ptr) \
    asm volatile("cp.async.cg.shared.global [%0], [%1], 16;" \
        :: "r"(dst_u32), "l"(src_ptr) : "memory")

#define CP_COMMIT() asm volatile("cp.async.commit_group;" ::: "memory")
#define CP_WAIT_ALL() asm volatile("cp.async.wait_group 0;" ::: "memory")
#define CP_WAIT_1() asm volatile("cp.async.wait_group 1;" ::: "memory")

__device__ __forceinline__ uint32_t smem_u32_of(const void* p) {
    uint32_t a;
    asm("{ .reg .u64 t; cvta.to.shared.u64 t, %1; cvt.u32.u64 %0, t; }"
        : "=r"(a) : "l"(p));
    return a;
}

// ---------------- fp16 GEMM: cp.async 3-stage + ldmatrix (round-15) ---------
#define GEMM_NTHREADS 256
#define GSTR 40
#define STAGE_BYTES (2*128*GSTR*2)            // 20480
#define GEMM_SMEM_BYTES (3*STAGE_BYTES)       // 61440

__device__ __forceinline__ void gemm_f16_mainloop(
    const __half* __restrict__ Ag, const __half* __restrict__ Bg,
    int K, uint32_t smb, float (&acc)[4][4][4])
{
    const int tid = threadIdx.x;
    const int lane = tid & 31;
    const int wid = tid >> 5;
    const int mwarp = wid >> 2;
    const int nwarp = wid & 3;
    const int KT = K >> 5;

    const int crow0 = tid >> 2;                    // 0..63
    const int crow1 = crow0 + 64;
    const int cc8 = (tid & 3) * 8;
    const uint32_t cdst0 = (uint32_t)(crow0 * GSTR + cc8) * 2;
    const uint32_t cdst1 = (uint32_t)(crow1 * GSTR + cc8) * 2;

    const int lrow = lane & 7;
    const int lj = lane >> 3;
    const uint32_t aOffBase = (uint32_t)(((mwarp * 64 + lrow + (lj & 1) * 8) * GSTR +
                                          (lj >> 1) * 8) * 2);
    const uint32_t bOffBase = (uint32_t)(((nwarp * 16 + lrow + (lj >> 1) * 8) * GSTR +
                                          (lj & 1) * 8) * 2);

    auto issue = [&](int t) {
        const uint32_t sb = smb + (uint32_t)(t % 3) * STAGE_BYTES;
        const __half* As = Ag + (size_t)t * 32;
        const __half* Bs = Bg + (size_t)t * 32;
        CP_ASYNC16(sb + cdst0, As + (size_t)crow0 * K + cc8);
        CP_ASYNC16(sb + cdst1, As + (size_t)crow1 * K + cc8);
        CP_ASYNC16(sb + STAGE_BYTES/2 + cdst0, Bs + (size_t)crow0 * K + cc8);
        CP_ASYNC16(sb + STAGE_BYTES/2 + cdst1, Bs + (size_t)crow1 * K + cc8);
        CP_COMMIT();
    };

    issue(0);
    if (KT > 1) issue(1);

    for (int t = 0; t < KT; t++) {
        CP_WAIT_1();
        __syncthreads();
        if (t + 2 < KT) issue(t + 2);

        const uint32_t sb = smb + (uint32_t)(t % 3) * STAGE_BYTES;
        const uint32_t aB = sb + aOffBase;
        const uint32_t bB = sb + STAGE_BYTES/2 + bOffBase;

        #pragma unroll
        for (int ks = 0; ks < 2; ks++) {
            const uint32_t kofs = (uint32_t)(ks * 32);
            unsigned a4[4][4];
            #pragma unroll
            for (int mt = 0; mt < 4; mt++)
                LDSM_X4(a4[mt][0], a4[mt][1], a4[mt][2], a4[mt][3],
                        aB + (uint32_t)(mt * 16 * GSTR * 2) + kofs);
            #pragma unroll
            for (int grp = 0; grp < 2; grp++) {
                unsigned b0, b1, b2, b3;
                LDSM_X4(b0, b1, b2, b3,
                        bB + (uint32_t)(grp * 64 * GSTR * 2) + kofs);
                #pragma unroll
                for (int mt = 0; mt < 4; mt++) {
                    mma_f16_r(acc[mt][grp * 2],     a4[mt], b0, b1);
                    mma_f16_r(acc[mt][grp * 2 + 1], a4[mt], b2, b3);
                }
            }
        }
        __syncthreads();
    }
}

// ---------------- QKV GEMM with fused bias + RoPE + fp16 scatter ------------
__global__ void __launch_bounds__(GEMM_NTHREADS, 2) qkv_gemm_kernel(
    const float* __restrict__ bias)
{
    extern __shared__ __align__(16) char smem[];
    const uint32_t smb = smem_u32_of(smem);
    float acc[4][4][4];
    #pragma unroll
    for (int i = 0; i < 4; i++)
        #pragma unroll
        for (int j = 0; j < 4; j++)
            #pragma unroll
            for (int k = 0; k < 4; k++) acc[i][j][k] = 0.f;

    const int m0 = blockIdx.y * 128;
    const int n0 = blockIdx.x * 128;
    gemm_f16_mainloop(g_Xh + (size_t)m0 * DM, g_Wqkvh + (size_t)n0 * DM,
                      DM, smb, acc);

    const int tid = threadIdx.x;
    const int lane = tid & 31;
    const int wid = tid >> 5;
    const int g = lane >> 2, c = lane & 3;
    const int mwarp = wid >> 2, nwarp = wid & 3;

    const int comp = n0 >> 11;            // 0=Q, 1=K, 2=V
    const int h = (n0 >> 7) & 15;
    __half* dst = (comp == 0) ? g_Qh : (comp == 1) ? g_Kh : g_Vh;

    #pragma unroll
    for (int mt = 0; mt < 4; mt++) {
        #pragma unroll
        for (int rr = 0; rr < 2; rr++) {
            int m = m0 + mwarp * 64 + mt * 16 + g + rr * 8;
            int bb = m >> 11, s = m & 2047;
            size_t base = ((size_t)(bb * NH + h) * SEQ + s) * HD;
            #pragma unroll
            for (int ntp = 0; ntp < 2; ntp++) {
                int d0 = nwarp * 16 + ntp * 8 + 2 * c;       // 0..63
                float v0e0 = acc[mt][ntp][rr * 2]     + bias[n0 + d0];
                float v0e1 = acc[mt][ntp][rr * 2 + 1] + bias[n0 + d0 + 1];
                float v1e0 = acc[mt][ntp + 2][rr * 2]     + bias[n0 + 64 + d0];
                float v1e1 = acc[mt][ntp + 2][rr * 2 + 1] + bias[n0 + 64 + d0 + 1];
                if (comp == 2) {
                    *(__half2*)&dst[base + d0]      = __floats2half2_rn(v0e0, v0e1);
                    *(__half2*)&dst[base + 64 + d0] = __floats2half2_rn(v1e0, v1e1);
                } else {
                    float2 cs = *(const float2*)&g_cos[s * 64 + d0];
                    float2 sn = *(const float2*)&g_sin[s * 64 + d0];
                    float q0e0 = v0e0 * cs.x - v1e0 * sn.x;
                    float q0e1 = v0e1 * cs.y - v1e1 * sn.y;
                    float q1e0 = v1e0 * cs.x + v0e0 * sn.x;
                    float q1e1 = v1e1 * cs.y + v0e1 * sn.y;
                    *(__half2*)&dst[base + d0]      = __floats2half2_rn(q0e0, q0e1);
                    *(__half2*)&dst[base + 64 + d0] = __floats2half2_rn(q1e0, q1e1);
                }
            }
        }
    }
}

// ---------------- output projection GEMM (reads g_ctxh) ---------------------
__global__ void __launch_bounds__(GEMM_NTHREADS, 2) out_gemm_kernel(
    const float* __restrict__ bias, float* __restrict__ C)
{
    extern __shared__ __align__(16) char smem[];
    const uint32_t smb = smem_u32_of(smem);
    float acc[4][4][4];
    #pragma unroll
    for (int i = 0; i < 4; i++)
        #pragma unroll
        for (int j = 0; j < 4; j++)
            #pragma unroll
            for (int k = 0; k < 4; k++) acc[i][j][k] = 0.f;

    const int m0 = blockIdx.y * 128;
    const int n0 = blockIdx.x * 128;
    gemm_f16_mainloop(g_ctxh + (size_t)m0 * DM, g_OWh + (size_t)n0 * DM,
                      DM, smb, acc);

    const int tid = threadIdx.x;
    const int lane = tid & 31;
    const int wid = tid >> 5;
    const int g = lane >> 2, c = lane & 3;
    const int mwarp = wid >> 2, nwarp = wid & 3;

    #pragma unroll
    for (int mt = 0; mt < 4; mt++) {
        #pragma unroll
        for (int rr = 0; rr < 2; rr++) {
            int row = m0 + mwarp * 64 + mt * 16 + g + rr * 8;
            #pragma unroll
            for (int nt = 0; nt < 4; nt++) {
                int colb = n0 + nwarp * 16 + (nt & 1) * 8 + (nt >> 1) * 64 + 2 * c;
                float2 st;
                st.x = acc[mt][nt][rr * 2]     + bias[colb];
                st.y = acc[mt][nt][rr * 2 + 1] + bias[colb + 1];
                *(float2*)(C + (size_t)row * DM + colb) = st;
            }
        }
    }
}

// ---------------- flash attention: single-fp16, cp.async, ldmatrix ----------
// BM=128, BN=64, D=128. smem: Q[128][ASTR] + 2 x (K[64][ASTR] + V[64][ASTR])
// fp16 -> 104 KB total -> 2 CTAs/SM. P packed to fp16 in registers.
#define ASTR 136
#define SM_Q 0
#define SM_KV (128*ASTR)               // ushort index
#define KV_BUF (2*64*ASTR)             // 17408 ushorts per buffer
#define ATTN_SMEM_BYTES ((SM_KV + 2*KV_BUF) * 2)   // 104448

__global__ void __launch_bounds__(256, 2) attn_mma_kernel() {
    extern __shared__ __align__(16) unsigned short sm[];
    const uint32_t smb = smem_u32_of(sm);

    const int tid = threadIdx.x;
    const int lane = tid & 31;
    const int wid = tid >> 5;
    const int g = lane >> 2;           // 0..7
    const int c = lane & 3;            // 0..3
    const int m0 = wid * 16;
    const int qb = blockIdx.x;         // 0..15
    const int bh = blockIdx.y;         // 0..31
    const int b = bh >> 4, h = bh & 15;

    const size_t bhoff = (size_t)bh * SEQ * HD;
    const __half* Qg = g_Qh + bhoff + (size_t)qb * 128 * HD;
    const __half* Kg0 = g_Kh + bhoff;
    const __half* Vg0 = g_Vh + bhoff;

    // ---- load Q (128x128 fp16, straight copy) ----
    #pragma unroll
    for (int it = 0; it < 8; it++) {
        int idx = tid + it * 256;                 // 0..2047
        int row = idx >> 4, d = (idx & 15) * 8;
        *(uint4*)&sm[SM_Q + row * ASTR + d] =
            *(const uint4*)((const unsigned short*)Qg + (size_t)row * HD + d);
    }

    const int lrow = lane & 7;
    const int lj = lane >> 3;
    const uint32_t qA = smb + SM_Q * 2 +
        (uint32_t)(((m0 + lrow + (lj & 1) * 8) * ASTR + (lj >> 1) * 8) * 2);
    const uint32_t kB_off = (uint32_t)(((lrow + (lj >> 1) * 8) * ASTR +
                                        (lj & 1) * 8) * 2);
    const uint32_t vB_off = (uint32_t)(((lrow + (lj & 1) * 8) * ASTR +
                                        (lj >> 1) * 8) * 2);

    float o[16][4];
    float mrow[2], lrow2[2];
    #pragma unroll
    for (int i = 0; i < 16; i++)
        #pragma unroll
        for (int j = 0; j < 4; j++) o[i][j] = 0.f;
    mrow[0] = mrow[1] = -1e30f;
    lrow2[0] = lrow2[1] = 0.f;

    const int r0 = qb * 128 + m0 + g;
    const int r1 = r0 + 8;
    const int kbmax = 2 * qb + 1;

    auto issue_kv = [&](int buf, int kb) {
        const size_t koff = (size_t)kb * 64 * HD;
        const uint32_t base = smb + (uint32_t)(SM_KV + buf * KV_BUF) * 2;
        #pragma unroll
        for (int it = 0; it < 4; it++) {
            int chunk = tid + it * 256;           // 0..1023
            int row = chunk >> 4;
            int d8 = (chunk & 15) * 8;
            uint32_t doff = (uint32_t)(row * ASTR + d8) * 2;
            size_t soff = koff + (size_t)row * HD + d8;
            CP_ASYNC16(base + doff,                Kg0 + soff);
            CP_ASYNC16(base + (64u*ASTR)*2 + doff, Vg0 + soff);
        }
        CP_COMMIT();
    };

    issue_kv(0, 0);

    for (int kb = 0; kb <= kbmax; kb++) {
        const int buf = kb & 1;
        CP_WAIT_ALL();
        __syncthreads();
        if (kb + 1 <= kbmax) issue_kv(buf ^ 1, kb + 1);

        const uint32_t kvb = smb + (uint32_t)(SM_KV + buf * KV_BUF) * 2;
        const uint32_t kBb = kvb + kB_off;
        const uint32_t vBb = kvb + (64u * ASTR) * 2 + vB_off;

        // ---- S = Q @ K^T ----
        float sacc[8][4];
        #pragma unroll
        for (int nt = 0; nt < 8; nt++)
            #pragma unroll
            for (int e = 0; e < 4; e++) sacc[nt][e] = 0.f;

        #pragma unroll
        for (int ks = 0; ks < 8; ks++) {
            const uint32_t k0b = (uint32_t)(ks * 32);
            unsigned a4[4];
            LDSM_X4(a4[0], a4[1], a4[2], a4[3], qA + k0b);
            #pragma unroll
            for (int ntp = 0; ntp < 4; ntp++) {
                const uint32_t rowb = (uint32_t)(ntp * 16 * ASTR * 2);
                unsigned k0, k1, k2, k3;
                LDSM_X4(k0, k1, k2, k3, kBb + rowb + k0b);
                mma_f16_r(sacc[2*ntp],   a4, k0, k1);
                mma_f16_r(sacc[2*ntp+1], a4, k2, k3);
            }
        }

        // ---- scale + causal mask + online softmax ----
        float smax0 = -1e30f, smax1 = -1e30f;
        #pragma unroll
        for (int nt = 0; nt < 8; nt++) {
            int col = kb * 64 + nt * 8 + 2 * c;
            float v00 = sacc[nt][0] * SCALE; if (col     > r0) v00 = -1e30f;
            float v01 = sacc[nt][1] * SCALE; if (col + 1 > r0) v01 = -1e30f;
            float v10 = sacc[nt][2] * SCALE; if (col     > r1) v10 = -1e30f;
            float v11 = sacc[nt][3] * SCALE; if (col + 1 > r1) v11 = -1e30f;
            sacc[nt][0] = v00; sacc[nt][1] = v01;
            sacc[nt][2] = v10; sacc[nt][3] = v11;
            smax0 = fmaxf(smax0, fmaxf(v00, v01));
            smax1 = fmaxf(smax1, fmaxf(v10, v11));
        }
        smax0 = fmaxf(smax0, __shfl_xor_sync(0xffffffffu, smax0, 1));
        smax0 = fmaxf(smax0, __shfl_xor_sync(0xffffffffu, smax0, 2));
        smax1 = fmaxf(smax1, __shfl_xor_sync(0xffffffffu, smax1, 1));
        smax1 = fmaxf(smax1, __shfl_xor_sync(0xffffffffu, smax1, 2));

        float mnew0 = fmaxf(mrow[0], smax0);
        float mnew1 = fmaxf(mrow[1], smax1);
        float corr0 = __expf(mrow[0] - mnew0);
        float corr1 = __expf(mrow[1] - mnew1);
        mrow[0] = mnew0; mrow[1] = mnew1;

        float rsum0 = 0.f, rsum1 = 0.f;
        #pragma unroll
        for (int nt = 0; nt < 8; nt++) {
            float p00 = __expf(sacc[nt][0] - mnew0);
            float p01 = __expf(sacc[nt][1] - mnew0);
            float p10 = __expf(sacc[nt][2] - mnew1);
            float p11 = __expf(sacc[nt][3] - mnew1);
            rsum0 += p00 + p01;
            rsum1 += p10 + p11;
            sacc[nt][0] = p00; sacc[nt][1] = p01;
            sacc[nt][2] = p10; sacc[nt][3] = p11;
        }
        rsum0 += __shfl_xor_sync(0xffffffffu, rsum0, 1);
        rsum0 += __shfl_xor_sync(0xffffffffu, rsum0, 2);
        rsum1 += __shfl_xor_sync(0xffffffffu, rsum1, 1);
        rsum1 += __shfl_xor_sync(0xffffffffu, rsum1, 2);
        lrow2[0] = lrow2[0] * corr0 + rsum0;
        lrow2[1] = lrow2[1] * corr1 + rsum1;

        #pragma unroll
        for (int nt = 0; nt < 16; nt++) {
            o[nt][0] *= corr0; o[nt][1] *= corr0;
            o[nt][2] *= corr1; o[nt][3] *= corr1;
        }

        // ---- O += P @ V  (P packed to fp16 directly from sacc) ----
        #pragma unroll
        for (int ks = 0; ks < 4; ks++) {
            unsigned pa[4];
            pa[0] = f2h2u(sacc[2*ks][0],   sacc[2*ks][1]);
            pa[1] = f2h2u(sacc[2*ks][2],   sacc[2*ks][3]);
            pa[2] = f2h2u(sacc[2*ks+1][0], sacc[2*ks+1][1]);
            pa[3] = f2h2u(sacc[2*ks+1][2], sacc[2*ks+1][3]);
            const uint32_t srowb = (uint32_t)(ks * 16 * ASTR * 2);
            #pragma unroll
            for (int ntp = 0; ntp < 8; ntp++) {
                const uint32_t dcolb = (uint32_t)(ntp * 16 * 2);
                unsigned v0, v1, v2, v3;
                LDSM_X4_T(v0, v1, v2, v3, vBb + srowb + dcolb);
                mma_f16_r(o[2*ntp],   pa, v0, v1);
                mma_f16_r(o[2*ntp+1], pa, v2, v3);
            }
        }
    }

    // ---- normalize + write ctx as fp16 ----
    float inv0 = 1.0f / lrow2[0];
    float inv1 = 1.0f / lrow2[1];
    int s0 = qb * 128 + m0 + g;
    size_t base0 = ((size_t)b * SEQ + s0) * DM + h * HD;
    size_t base1 = ((size_t)b * SEQ + s0 + 8) * DM + h * HD;
    #pragma unroll
    for (int nt = 0; nt < 16; nt++) {
        int d0 = nt * 8 + 2 * c;
        *(__half2*)&g_ctxh[base0 + d0] =
            __floats2half2_rn(o[nt][0] * inv0, o[nt][1] * inv0);
        *(__half2*)&g_ctxh[base1 + d0] =
            __floats2half2_rn(o[nt][2] * inv1, o[nt][3] * inv1);
    }
}

// ---------------- launch ----------------------------------------------------
extern "C" void kernel_launch(void* const* d_in, const int* in_sizes, int n_in,
                              void* d_out, int out_size) {
    const float* x      = (const float*)d_in[0];
    // d_in[1] = attn_mask (causal, recomputed on the fly; unused)
    const float* Wqkv_w = (const float*)d_in[2];
    const float* Wqkv_b = (const float*)d_in[3];
    const float* out_w  = (const float*)d_in[4];
    const float* out_b  = (const float*)d_in[5];
    float* out = (float*)d_out;

    build_rope_kernel<<<(SEQ * 64 + 255) / 256, 256>>>();

    __half* xh;  cudaGetSymbolAddress((void**)&xh,  g_Xh);
    __half* wh;  cudaGetSymbolAddress((void**)&wh,  g_Wqkvh);
    __half* owh; cudaGetSymbolAddress((void**)&owh, g_OWh);
    cvt_h_kernel<<<592, 256>>>(x, xh, MROWS * DM / 4);
    cvt_h_kernel<<<592, 256>>>(Wqkv_w, wh, NQKV * DM / 4);
    cvt_h_kernel<<<592, 256>>>(out_w, owh, DM * DM / 4);

    cudaFuncSetAttribute(qkv_gemm_kernel,
                         cudaFuncAttributeMaxDynamicSharedMemorySize, GEMM_SMEM_BYTES);
    cudaFuncSetAttribute(out_gemm_kernel,
                         cudaFuncAttributeMaxDynamicSharedMemorySize, GEMM_SMEM_BYTES);

    qkv_gemm_kernel<<<dim3(NQKV / 128, MROWS / 128), GEMM_NTHREADS,
                      GEMM_SMEM_BYTES>>>(Wqkv_b);

    cudaFuncSetAttribute(attn_mma_kernel,
                         cudaFuncAttributeMaxDynamicSharedMemorySize, ATTN_SMEM_BYTES);
    attn_mma_kernel<<<dim3(SEQ / 128, BATCH * NH), 256, ATTN_SMEM_BYTES>>>();

    out_gemm_kernel<<<dim3(DM / 128, MROWS / 128), GEMM_NTHREADS,
                      GEMM_SMEM_BYTES>>>(out_b, out);
}

// round 17
// speedup vs baseline: 2.6549x; 1.0232x over previous
#include <cuda_runtime.h>
#include <cuda_bf16.h>
#include <cuda_fp16.h>
#include <cstdint>
#include <stdint.h>
#include <math.h>

#define BATCH 2
#define SEQ 2048
#define NH 16
#define HD 128
#define DM 2048
#define MROWS (BATCH*SEQ)     // 4096
#define NQKV (3*DM)           // 6144
#define SCALE 0.08838834764831845f  // 1/sqrt(128)

// ---------------- scratch (static device globals: allocation-free) ----------
__device__ __half g_Qh[BATCH*NH*SEQ*HD];   // fp16 Q/K/V [b,h,s,d]
__device__ __half g_Kh[BATCH*NH*SEQ*HD];
__device__ __half g_Vh[BATCH*NH*SEQ*HD];
__device__ __half g_ctxh[MROWS*DM];        // ctx, fp16 (written by attention)
__device__ __half g_Xh[MROWS*DM];          // fp16 copies of GEMM operands
__device__ __half g_Wqkvh[NQKV*DM];
__device__ __half g_OWh[DM*DM];
__device__ float g_cos[SEQ*64];
__device__ float g_sin[SEQ*64];

// ---------------- RoPE table -------------------------------------------------
__global__ void build_rope_kernel() {
    int idx = blockIdx.x * blockDim.x + threadIdx.x;
    if (idx >= SEQ * 64) return;
    int pos = idx >> 6, i = idx & 63;
    double f = pow(10000.0, -(double)i / 64.0);
    double a = (double)pos * f;
    g_cos[idx] = (float)cos(a);
    g_sin[idx] = (float)sin(a);
}

// ---------------- fused fp32 -> fp16 pre-convert (all 3 operands) -----------
#define CVT_N1 (MROWS*DM/4)
#define CVT_N2 (NQKV*DM/4)
#define CVT_N3 (DM*DM/4)
__global__ void cvt_all_kernel(const float* __restrict__ s1,
                               const float* __restrict__ s2,
                               const float* __restrict__ s3,
                               __half* __restrict__ d1,
                               __half* __restrict__ d2,
                               __half* __restrict__ d3) {
    int i = blockIdx.x * blockDim.x + threadIdx.x;
    int stride = gridDim.x * blockDim.x;
    const int total = CVT_N1 + CVT_N2 + CVT_N3;
    for (; i < total; i += stride) {
        const float* src; __half* dst; int j;
        if (i < CVT_N1)             { src = s1; dst = d1; j = i; }
        else if (i < CVT_N1+CVT_N2) { src = s2; dst = d2; j = i - CVT_N1; }
        else                        { src = s3; dst = d3; j = i - CVT_N1 - CVT_N2; }
        float4 v = *(const float4*)(src + (size_t)j * 4);
        *(__half2*)(dst + (size_t)j * 4)     = __floats2half2_rn(v.x, v.y);
        *(__half2*)(dst + (size_t)j * 4 + 2) = __floats2half2_rn(v.z, v.w);
    }
}

// ---------------- mma / ldmatrix / cp.async helpers --------------------------
__device__ __forceinline__ void mma_f16_r(float (&cacc)[4],
                                          const unsigned (&a)[4],
                                          unsigned b0, unsigned b1) {
    asm volatile(
        "mma.sync.aligned.m16n8k16.row.col.f32.f16.f16.f32 "
        "{%0,%1,%2,%3}, {%4,%5,%6,%7}, {%8,%9}, {%0,%1,%2,%3};\n"
        : "+f"(cacc[0]), "+f"(cacc[1]), "+f"(cacc[2]), "+f"(cacc[3])
        : "r"(a[0]), "r"(a[1]), "r"(a[2]), "r"(a[3]), "r"(b0), "r"(b1));
}

__device__ __forceinline__ unsigned f2h2u(float lo, float hi) {
    __half2 h = __floats2half2_rn(lo, hi);
    return *(unsigned*)&h;
}

#define LDSM_X4(r0, r1, r2, r3, addr) \
    asm volatile("ldmatrix.sync.aligned.m8n8.x4.shared.b16 {%0,%1,%2,%3}, [%4];" \
        : "=r"(r0), "=r"(r1), "=r"(r2), "=r"(r3) : "r"(addr))

#define LDSM_X4_T(r0, r1, r2, r3, addr) \
    asm volatile("ldmatrix.sync.aligned.m8n8.x4.trans.shared.b16 {%0,%1,%2,%3}, [%4];" \
        : "=r"(r0), "=r"(r1), "=r"(r2), "=r"(r3) : "r"(addr))

#define CP_ASYNC16(dst_u32, src_ptr) \
    asm volatile("cp.async.cg.shared.global [%0], [%1], 16;" \
        :: "r"(dst_u32), "l"(src_ptr) : "memory")

#define CP_COMMIT() asm volatile("cp.async.commit_group;" ::: "memory")
#define CP_WAIT_ALL() asm volatile("cp.async.wait_group 0;" ::: "memory")
#define CP_WAIT_1() asm volatile("cp.async.wait_group 1;" ::: "memory")

__device__ __forceinline__ uint32_t smem_u32_of(const void* p) {
    uint32_t a;
    asm("{ .reg .u64 t; cvta.to.shared.u64 t, %1; cvt.u32.u64 %0, t; }"
        : "=r"(a) : "l"(p));
    return a;
}

// ---------------- fp16 GEMM: cp.async 3-stage + ldmatrix ---------------------
// Single barrier per tile: the top __syncthreads of iteration t already
// orders compute(t-1) (all warps) before issue(t+2) overwrites stage (t-1)%3.
#define GEMM_NTHREADS 256
#define GSTR 40
#define STAGE_BYTES (2*128*GSTR*2)            // 20480
#define GEMM_SMEM_BYTES (3*STAGE_BYTES)       // 61440

__device__ __forceinline__ void gemm_f16_mainloop(
    const __half* __restrict__ Ag, const __half* __restrict__ Bg,
    int K, uint32_t smb, float (&acc)[4][4][4])
{
    const int tid = threadIdx.x;
    const int lane = tid & 31;
    const int wid = tid >> 5;
    const int mwarp = wid >> 2;
    const int nwarp = wid & 3;
    const int KT = K >> 5;

    const int crow0 = tid >> 2;                    // 0..63
    const int crow1 = crow0 + 64;
    const int cc8 = (tid & 3) * 8;
    const uint32_t cdst0 = (uint32_t)(crow0 * GSTR + cc8) * 2;
    const uint32_t cdst1 = (uint32_t)(crow1 * GSTR + cc8) * 2;

    const int lrow = lane & 7;
    const int lj = lane >> 3;
    const uint32_t aOffBase = (uint32_t)(((mwarp * 64 + lrow + (lj & 1) * 8) * GSTR +
                                          (lj >> 1) * 8) * 2);
    const uint32_t bOffBase = (uint32_t)(((nwarp * 16 + lrow + (lj >> 1) * 8) * GSTR +
                                          (lj & 1) * 8) * 2);

    auto issue = [&](int t) {
        const uint32_t sb = smb + (uint32_t)(t % 3) * STAGE_BYTES;
        const __half* As = Ag + (size_t)t * 32;
        const __half* Bs = Bg + (size_t)t * 32;
        CP_ASYNC16(sb + cdst0, As + (size_t)crow0 * K + cc8);
        CP_ASYNC16(sb + cdst1, As + (size_t)crow1 * K + cc8);
        CP_ASYNC16(sb + STAGE_BYTES/2 + cdst0, Bs + (size_t)crow0 * K + cc8);
        CP_ASYNC16(sb + STAGE_BYTES/2 + cdst1, Bs + (size_t)crow1 * K + cc8);
        CP_COMMIT();
    };

    issue(0);
    if (KT > 1) issue(1);

    for (int t = 0; t < KT; t++) {
        CP_WAIT_1();
        __syncthreads();
        if (t + 2 < KT) issue(t + 2);

        const uint32_t sb = smb + (uint32_t)(t % 3) * STAGE_BYTES;
        const uint32_t aB = sb + aOffBase;
        const uint32_t bB = sb + STAGE_BYTES/2 + bOffBase;

        #pragma unroll
        for (int ks = 0; ks < 2; ks++) {
            const uint32_t kofs = (uint32_t)(ks * 32);
            unsigned a4[4][4];
            #pragma unroll
            for (int mt = 0; mt < 4; mt++)
                LDSM_X4(a4[mt][0], a4[mt][1], a4[mt][2], a4[mt][3],
                        aB + (uint32_t)(mt * 16 * GSTR * 2) + kofs);
            #pragma unroll
            for (int grp = 0; grp < 2; grp++) {
                unsigned b0, b1, b2, b3;
                LDSM_X4(b0, b1, b2, b3,
                        bB + (uint32_t)(grp * 64 * GSTR * 2) + kofs);
                #pragma unroll
                for (int mt = 0; mt < 4; mt++) {
                    mma_f16_r(acc[mt][grp * 2],     a4[mt], b0, b1);
                    mma_f16_r(acc[mt][grp * 2 + 1], a4[mt], b2, b3);
                }
            }
        }
    }
}

// ---------------- QKV GEMM with fused bias + RoPE + fp16 scatter ------------
__global__ void __launch_bounds__(GEMM_NTHREADS, 2) qkv_gemm_kernel(
    const float* __restrict__ bias)
{
    extern __shared__ __align__(16) char smem[];
    const uint32_t smb = smem_u32_of(smem);
    float acc[4][4][4];
    #pragma unroll
    for (int i = 0; i < 4; i++)
        #pragma unroll
        for (int j = 0; j < 4; j++)
            #pragma unroll
            for (int k = 0; k < 4; k++) acc[i][j][k] = 0.f;

    const int m0 = blockIdx.y * 128;
    const int n0 = blockIdx.x * 128;
    gemm_f16_mainloop(g_Xh + (size_t)m0 * DM, g_Wqkvh + (size_t)n0 * DM,
                      DM, smb, acc);

    const int tid = threadIdx.x;
    const int lane = tid & 31;
    const int wid = tid >> 5;
    const int g = lane >> 2, c = lane & 3;
    const int mwarp = wid >> 2, nwarp = wid & 3;

    const int comp = n0 >> 11;            // 0=Q, 1=K, 2=V
    const int h = (n0 >> 7) & 15;
    __half* dst = (comp == 0) ? g_Qh : (comp == 1) ? g_Kh : g_Vh;

    #pragma unroll
    for (int mt = 0; mt < 4; mt++) {
        #pragma unroll
        for (int rr = 0; rr < 2; rr++) {
            int m = m0 + mwarp * 64 + mt * 16 + g + rr * 8;
            int bb = m >> 11, s = m & 2047;
            size_t base = ((size_t)(bb * NH + h) * SEQ + s) * HD;
            #pragma unroll
            for (int ntp = 0; ntp < 2; ntp++) {
                int d0 = nwarp * 16 + ntp * 8 + 2 * c;       // 0..63
                float v0e0 = acc[mt][ntp][rr * 2]     + bias[n0 + d0];
                float v0e1 = acc[mt][ntp][rr * 2 + 1] + bias[n0 + d0 + 1];
                float v1e0 = acc[mt][ntp + 2][rr * 2]     + bias[n0 + 64 + d0];
                float v1e1 = acc[mt][ntp + 2][rr * 2 + 1] + bias[n0 + 64 + d0 + 1];
                if (comp == 2) {
                    *(__half2*)&dst[base + d0]      = __floats2half2_rn(v0e0, v0e1);
                    *(__half2*)&dst[base + 64 + d0] = __floats2half2_rn(v1e0, v1e1);
                } else {
                    float2 cs = *(const float2*)&g_cos[s * 64 + d0];
                    float2 sn = *(const float2*)&g_sin[s * 64 + d0];
                    float q0e0 = v0e0 * cs.x - v1e0 * sn.x;
                    float q0e1 = v0e1 * cs.y - v1e1 * sn.y;
                    float q1e0 = v1e0 * cs.x + v0e0 * sn.x;
                    float q1e1 = v1e1 * cs.y + v0e1 * sn.y;
                    *(__half2*)&dst[base + d0]      = __floats2half2_rn(q0e0, q0e1);
                    *(__half2*)&dst[base + 64 + d0] = __floats2half2_rn(q1e0, q1e1);
                }
            }
        }
    }
}

// ---------------- output projection GEMM (reads g_ctxh) ---------------------
__global__ void __launch_bounds__(GEMM_NTHREADS, 2) out_gemm_kernel(
    const float* __restrict__ bias, float* __restrict__ C)
{
    extern __shared__ __align__(16) char smem[];
    const uint32_t smb = smem_u32_of(smem);
    float acc[4][4][4];
    #pragma unroll
    for (int i = 0; i < 4; i++)
        #pragma unroll
        for (int j = 0; j < 4; j++)
            #pragma unroll
            for (int k = 0; k < 4; k++) acc[i][j][k] = 0.f;

    const int m0 = blockIdx.y * 128;
    const int n0 = blockIdx.x * 128;
    gemm_f16_mainloop(g_ctxh + (size_t)m0 * DM, g_OWh + (size_t)n0 * DM,
                      DM, smb, acc);

    const int tid = threadIdx.x;
    const int lane = tid & 31;
    const int wid = tid >> 5;
    const int g = lane >> 2, c = lane & 3;
    const int mwarp = wid >> 2, nwarp = wid & 3;

    #pragma unroll
    for (int mt = 0; mt < 4; mt++) {
        #pragma unroll
        for (int rr = 0; rr < 2; rr++) {
            int row = m0 + mwarp * 64 + mt * 16 + g + rr * 8;
            #pragma unroll
            for (int nt = 0; nt < 4; nt++) {
                int colb = n0 + nwarp * 16 + (nt & 1) * 8 + (nt >> 1) * 64 + 2 * c;
                float2 st;
                st.x = acc[mt][nt][rr * 2]     + bias[colb];
                st.y = acc[mt][nt][rr * 2 + 1] + bias[colb + 1];
                *(float2*)(C + (size_t)row * DM + colb) = st;
            }
        }
    }
}

// ---------------- flash attention: single-fp16, cp.async, ldmatrix ----------
// Longest-first scheduling: qb = 15 - blockIdx.x (work ~ qb; launch big first).
#define ASTR 136
#define SM_Q 0
#define SM_KV (128*ASTR)               // ushort index
#define KV_BUF (2*64*ASTR)             // 17408 ushorts per buffer
#define ATTN_SMEM_BYTES ((SM_KV + 2*KV_BUF) * 2)   // 104448

__global__ void __launch_bounds__(256, 2) attn_mma_kernel() {
    extern __shared__ __align__(16) unsigned short sm[];
    const uint32_t smb = smem_u32_of(sm);

    const int tid = threadIdx.x;
    const int lane = tid & 31;
    const int wid = tid >> 5;
    const int g = lane >> 2;           // 0..7
    const int c = lane & 3;            // 0..3
    const int m0 = wid * 16;
    const int qb = 15 - blockIdx.x;    // longest-first (LPT)
    const int bh = blockIdx.y;         // 0..31
    const int b = bh >> 4, h = bh & 15;

    const size_t bhoff = (size_t)bh * SEQ * HD;
    const __half* Qg = g_Qh + bhoff + (size_t)qb * 128 * HD;
    const __half* Kg0 = g_Kh + bhoff;
    const __half* Vg0 = g_Vh + bhoff;

    // ---- load Q (128x128 fp16, straight copy) ----
    #pragma unroll
    for (int it = 0; it < 8; it++) {
        int idx = tid + it * 256;                 // 0..2047
        int row = idx >> 4, d = (idx & 15) * 8;
        *(uint4*)&sm[SM_Q + row * ASTR + d] =
            *(const uint4*)((const unsigned short*)Qg + (size_t)row * HD + d);
    }

    const int lrow = lane & 7;
    const int lj = lane >> 3;
    const uint32_t qA = smb + SM_Q * 2 +
        (uint32_t)(((m0 + lrow + (lj & 1) * 8) * ASTR + (lj >> 1) * 8) * 2);
    const uint32_t kB_off = (uint32_t)(((lrow + (lj >> 1) * 8) * ASTR +
                                        (lj & 1) * 8) * 2);
    const uint32_t vB_off = (uint32_t)(((lrow + (lj & 1) * 8) * ASTR +
                                        (lj >> 1) * 8) * 2);

    float o[16][4];
    float mrow[2], lrow2[2];
    #pragma unroll
    for (int i = 0; i < 16; i++)
        #pragma unroll
        for (int j = 0; j < 4; j++) o[i][j] = 0.f;
    mrow[0] = mrow[1] = -1e30f;
    lrow2[0] = lrow2[1] = 0.f;

    const int r0 = qb * 128 + m0 + g;
    const int r1 = r0 + 8;
    const int kbmax = 2 * qb + 1;

    auto issue_kv = [&](int buf, int kb) {
        const size_t koff = (size_t)kb * 64 * HD;
        const uint32_t base = smb + (uint32_t)(SM_KV + buf * KV_BUF) * 2;
        #pragma unroll
        for (int it = 0; it < 4; it++) {
            int chunk = tid + it * 256;           // 0..1023
            int row = chunk >> 4;
            int d8 = (chunk & 15) * 8;
            uint32_t doff = (uint32_t)(row * ASTR + d8) * 2;
            size_t soff = koff + (size_t)row * HD + d8;
            CP_ASYNC16(base + doff,                Kg0 + soff);
            CP_ASYNC16(base + (64u*ASTR)*2 + doff, Vg0 + soff);
        }
        CP_COMMIT();
    };

    issue_kv(0, 0);

    for (int kb = 0; kb <= kbmax; kb++) {
        const int buf = kb & 1;
        CP_WAIT_ALL();
        __syncthreads();
        if (kb + 1 <= kbmax) issue_kv(buf ^ 1, kb + 1);

        const uint32_t kvb = smb + (uint32_t)(SM_KV + buf * KV_BUF) * 2;
        const uint32_t kBb = kvb + kB_off;
        const uint32_t vBb = kvb + (64u * ASTR) * 2 + vB_off;

        // ---- S = Q @ K^T ----
        float sacc[8][4];
        #pragma unroll
        for (int nt = 0; nt < 8; nt++)
            #pragma unroll
            for (int e = 0; e < 4; e++) sacc[nt][e] = 0.f;

        #pragma unroll
        for (int ks = 0; ks < 8; ks++) {
            const uint32_t k0b = (uint32_t)(ks * 32);
            unsigned a4[4];
            LDSM_X4(a4[0], a4[1], a4[2], a4[3], qA + k0b);
            #pragma unroll
            for (int ntp = 0; ntp < 4; ntp++) {
                const uint32_t rowb = (uint32_t)(ntp * 16 * ASTR * 2);
                unsigned k0, k1, k2, k3;
                LDSM_X4(k0, k1, k2, k3, kBb + rowb + k0b);
                mma_f16_r(sacc[2*ntp],   a4, k0, k1);
                mma_f16_r(sacc[2*ntp+1], a4, k2, k3);
            }
        }

        // ---- scale + causal mask + online softmax ----
        float smax0 = -1e30f, smax1 = -1e30f;
        #pragma unroll
        for (int nt = 0; nt < 8; nt++) {
            int col = kb * 64 + nt * 8 + 2 * c;
            float v00 = sacc[nt][0] * SCALE; if (col     > r0) v00 = -1e30f;
            float v01 = sacc[nt][1] * SCALE; if (col + 1 > r0) v01 = -1e30f;
            float v10 = sacc[nt][2] * SCALE; if (col     > r1) v10 = -1e30f;
            float v11 = sacc[nt][3] * SCALE; if (col + 1 > r1) v11 = -1e30f;
            sacc[nt][0] = v00; sacc[nt][1] = v01;
            sacc[nt][2] = v10; sacc[nt][3] = v11;
            smax0 = fmaxf(smax0, fmaxf(v00, v01));
            smax1 = fmaxf(smax1, fmaxf(v10, v11));
        }
        smax0 = fmaxf(smax0, __shfl_xor_sync(0xffffffffu, smax0, 1));
        smax0 = fmaxf(smax0, __shfl_xor_sync(0xffffffffu, smax0, 2));
        smax1 = fmaxf(smax1, __shfl_xor_sync(0xffffffffu, smax1, 1));
        smax1 = fmaxf(smax1, __shfl_xor_sync(0xffffffffu, smax1, 2));

        float mnew0 = fmaxf(mrow[0], smax0);
        float mnew1 = fmaxf(mrow[1], smax1);
        float corr0 = __expf(mrow[0] - mnew0);
        float corr1 = __expf(mrow[1] - mnew1);
        mrow[0] = mnew0; mrow[1] = mnew1;

        float rsum0 = 0.f, rsum1 = 0.f;
        #pragma unroll
        for (int nt = 0; nt < 8; nt++) {
            float p00 = __expf(sacc[nt][0] - mnew0);
            float p01 = __expf(sacc[nt][1] - mnew0);
            float p10 = __expf(sacc[nt][2] - mnew1);
            float p11 = __expf(sacc[nt][3] - mnew1);
            rsum0 += p00 + p01;
            rsum1 += p10 + p11;
            sacc[nt][0] = p00; sacc[nt][1] = p01;
            sacc[nt][2] = p10; sacc[nt][3] = p11;
        }
        rsum0 += __shfl_xor_sync(0xffffffffu, rsum0, 1);
        rsum0 += __shfl_xor_sync(0xffffffffu, rsum0, 2);
        rsum1 += __shfl_xor_sync(0xffffffffu, rsum1, 1);
        rsum1 += __shfl_xor_sync(0xffffffffu, rsum1, 2);
        lrow2[0] = lrow2[0] * corr0 + rsum0;
        lrow2[1] = lrow2[1] * corr1 + rsum1;

        #pragma unroll
        for (int nt = 0; nt < 16; nt++) {
            o[nt][0] *= corr0; o[nt][1] *= corr0;
            o[nt][2] *= corr1; o[nt][3] *= corr1;
        }

        // ---- O += P @ V  (P packed to fp16 directly from sacc) ----
        #pragma unroll
        for (int ks = 0; ks < 4; ks++) {
            unsigned pa[4];
            pa[0] = f2h2u(sacc[2*ks][0],   sacc[2*ks][1]);
            pa[1] = f2h2u(sacc[2*ks][2],   sacc[2*ks][3]);
            pa[2] = f2h2u(sacc[2*ks+1][0], sacc[2*ks+1][1]);
            pa[3] = f2h2u(sacc[2*ks+1][2], sacc[2*ks+1][3]);
            const uint32_t srowb = (uint32_t)(ks * 16 * ASTR * 2);
            #pragma unroll
            for (int ntp = 0; ntp < 8; ntp++) {
                const uint32_t dcolb = (uint32_t)(ntp * 16 * 2);
                unsigned v0, v1, v2, v3;
                LDSM_X4_T(v0, v1, v2, v3, vBb + srowb + dcolb);
                mma_f16_r(o[2*ntp],   pa, v0, v1);
                mma_f16_r(o[2*ntp+1], pa, v2, v3);
            }
        }
    }

    // ---- normalize + write ctx as fp16 ----
    float inv0 = 1.0f / lrow2[0];
    float inv1 = 1.0f / lrow2[1];
    int s0 = qb * 128 + m0 + g;
    size_t base0 = ((size_t)b * SEQ + s0) * DM + h * HD;
    size_t base1 = ((size_t)b * SEQ + s0 + 8) * DM + h * HD;
    #pragma unroll
    for (int nt = 0; nt < 16; nt++) {
        int d0 = nt * 8 + 2 * c;
        *(__half2*)&g_ctxh[base0 + d0] =
            __floats2half2_rn(o[nt][0] * inv0, o[nt][1] * inv0);
        *(__half2*)&g_ctxh[base1 + d0] =
            __floats2half2_rn(o[nt][2] * inv1, o[nt][3] * inv1);
    }
}

// ---------------- launch ----------------------------------------------------
extern "C" void kernel_launch(void* const* d_in, const int* in_sizes, int n_in,
                              void* d_out, int out_size) {
    const float* x      = (const float*)d_in[0];
    // d_in[1] = attn_mask (causal, recomputed on the fly; unused)
    const float* Wqkv_w = (const float*)d_in[2];
    const float* Wqkv_b = (const float*)d_in[3];
    const float* out_w  = (const float*)d_in[4];
    const float* out_b  = (const float*)d_in[5];
    float* out = (float*)d_out;

    build_rope_kernel<<<(SEQ * 64 + 255) / 256, 256>>>();

    __half* xh;  cudaGetSymbolAddress((void**)&xh,  g_Xh);
    __half* wh;  cudaGetSymbolAddress((void**)&wh,  g_Wqkvh);
    __half* owh; cudaGetSymbolAddress((void**)&owh, g_OWh);
    cvt_all_kernel<<<1184, 256>>>(x, Wqkv_w, out_w, xh, wh, owh);

    cudaFuncSetAttribute(qkv_gemm_kernel,
                         cudaFuncAttributeMaxDynamicSharedMemorySize, GEMM_SMEM_BYTES);
    cudaFuncSetAttribute(out_gemm_kernel,
                         cudaFuncAttributeMaxDynamicSharedMemorySize, GEMM_SMEM_BYTES);

    qkv_gemm_kernel<<<dim3(NQKV / 128, MROWS / 128), GEMM_NTHREADS,
                      GEMM_SMEM_BYTES>>>(Wqkv_b);

    cudaFuncSetAttribute(attn_mma_kernel,
                         cudaFuncAttributeMaxDynamicSharedMemorySize, ATTN_SMEM_BYTES);
    attn_mma_kernel<<<dim3(SEQ / 128, BATCH * NH), 256, ATTN_SMEM_BYTES>>>();

    out_gemm_kernel<<<dim3(DM / 128, MROWS / 128), GEMM_NTHREADS,
                      GEMM_SMEM_BYTES>>>(out_b, out);
}